// round 1
// baseline (speedup 1.0000x reference)
#include <cuda_runtime.h>
#include <math.h>

#define Bsz 2
#define Lsz 1024
#define Hsz 2048
#define Msz (Bsz*Lsz)          // 2048 rows
#define NST 16
#define DTR 64
#define CHUNK 128
#define NCHUNK (Lsz/CHUNK)     // 8
#define DBC_SPLITS 8

// ---------------- scratch (device globals; no runtime allocation) ----------------
__device__ float d_h[(size_t)Msz*Hsz];         // rmsnorm out
__device__ float d_xz[(size_t)Msz*2*Hsz];      // in_proj out (xc_pre | z)
__device__ float d_xc[(size_t)Msz*Hsz];        // conv+silu out
__device__ float d_dbc[(size_t)Msz*96];        // x_proj out
__device__ float d_dbcp[(size_t)DBC_SPLITS*Msz*96];
__device__ float d_delta[(size_t)Msz*Hsz];     // softplus(dt) out
__device__ float d_g[(size_t)Msz*Hsz];         // y * silu(z)
__device__ float d_Aexp[Hsz*NST];              // -exp(A_log)
__device__ float d_P[(size_t)Bsz*NCHUNK*Hsz*NST];  // chunk decay products
__device__ float d_S[(size_t)Bsz*NCHUNK*Hsz*NST];  // chunk local final states
__device__ float d_I[(size_t)Bsz*NCHUNK*Hsz*NST];  // chunk init states

// ---------------- small kernels ----------------
__global__ void aexp_kernel(const float* __restrict__ alog) {
    int i = blockIdx.x*256 + threadIdx.x;
    if (i < Hsz*NST) d_Aexp[i] = -expf(alog[i]);
}

__global__ void rmsnorm_kernel(const float* __restrict__ x, const float* __restrict__ w) {
    const int m = blockIdx.x;
    const float* xr = x + (size_t)m*Hsz;
    float ss = 0.f;
    for (int i = threadIdx.x*4; i < Hsz; i += 1024) {
        float4 v = *(const float4*)(xr + i);
        ss += v.x*v.x + v.y*v.y + v.z*v.z + v.w*v.w;
    }
    __shared__ float red[8];
    #pragma unroll
    for (int o = 16; o; o >>= 1) ss += __shfl_xor_sync(0xffffffffu, ss, o);
    if ((threadIdx.x & 31) == 0) red[threadIdx.x >> 5] = ss;
    __syncthreads();
    if (threadIdx.x == 0) {
        float v = 0.f;
        #pragma unroll
        for (int j = 0; j < 8; j++) v += red[j];
        red[0] = rsqrtf(v * (1.0f/Hsz) + 1e-5f);
    }
    __syncthreads();
    const float sc = red[0];
    float* hr = d_h + (size_t)m*Hsz;
    for (int i = threadIdx.x*4; i < Hsz; i += 1024) {
        float4 v = *(const float4*)(xr + i);
        float4 wv = *(const float4*)(w + i);
        v.x *= sc*wv.x; v.y *= sc*wv.y; v.z *= sc*wv.z; v.w *= sc*wv.w;
        *(float4*)(hr + i) = v;
    }
}

// ---------------- generic GEMM: C = A(M,K;lda) * W(N,K;ldb)^T ----------------
// EPI 0: plain store; 2: softplus(acc+bias); 3: acc + resid; 4: split-K partial (n<N guard)
template<int EPI>
__global__ void __launch_bounds__(256)
gemm_wt(const float* __restrict__ A, const float* __restrict__ W,
        float* __restrict__ C, int M, int N, int K,
        int lda, int ldb, int ldc,
        const float* __restrict__ bias, const float* __restrict__ resid)
{
    __shared__ float As[8][128];
    __shared__ float Bs[8][128];
    const int t  = threadIdx.x;
    const int n0 = blockIdx.x * 128;
    const int m0 = blockIdx.y * 128;
    const int kslice = K / gridDim.z;
    const int kbeg = blockIdx.z * kslice;
    const int KT = kslice >> 3;

    const int ar = t >> 1;
    const int ak = (t & 1) * 4;
    const float* Ap = A + (size_t)(m0 + ar)*lda + kbeg + ak;
    const bool wok = (n0 + ar) < N;
    const float* Wp = W + (size_t)(n0 + ar)*ldb + kbeg + ak;

    float* Cb = C;
    if (EPI == 4) Cb = C + (size_t)blockIdx.z * M * ldc;

    const int tx = t & 15, ty = t >> 4;
    float acc[8][8];
    #pragma unroll
    for (int i = 0; i < 8; i++)
        #pragma unroll
        for (int j = 0; j < 8; j++) acc[i][j] = 0.f;

    float4 pa = *(const float4*)Ap;
    float4 pb = wok ? *(const float4*)Wp : make_float4(0.f,0.f,0.f,0.f);

    for (int kt = 0; kt < KT; ++kt) {
        As[ak+0][ar]=pa.x; As[ak+1][ar]=pa.y; As[ak+2][ar]=pa.z; As[ak+3][ar]=pa.w;
        Bs[ak+0][ar]=pb.x; Bs[ak+1][ar]=pb.y; Bs[ak+2][ar]=pb.z; Bs[ak+3][ar]=pb.w;
        __syncthreads();
        if (kt + 1 < KT) {
            pa = *(const float4*)(Ap + (size_t)(kt+1)*8);
            pb = wok ? *(const float4*)(Wp + (size_t)(kt+1)*8) : make_float4(0.f,0.f,0.f,0.f);
        }
        #pragma unroll
        for (int kk = 0; kk < 8; kk++) {
            float a[8], b[8];
            *(float4*)&a[0] = *(const float4*)&As[kk][ty*8];
            *(float4*)&a[4] = *(const float4*)&As[kk][ty*8+4];
            *(float4*)&b[0] = *(const float4*)&Bs[kk][tx*8];
            *(float4*)&b[4] = *(const float4*)&Bs[kk][tx*8+4];
            #pragma unroll
            for (int i = 0; i < 8; i++)
                #pragma unroll
                for (int j = 0; j < 8; j++)
                    acc[i][j] = fmaf(a[i], b[j], acc[i][j]);
        }
        __syncthreads();
    }

    #pragma unroll
    for (int i = 0; i < 8; i++) {
        const int m = m0 + ty*8 + i;
        #pragma unroll
        for (int j = 0; j < 8; j++) {
            const int n = n0 + tx*8 + j;
            if (n < N) {
                float v = acc[i][j];
                if (EPI == 2) { v += bias[n]; v = (v > 20.f) ? v : log1pf(__expf(v)); }
                if (EPI == 3) { v += resid[(size_t)m*ldc + n]; }
                Cb[(size_t)m*ldc + n] = v;
            }
        }
    }
}

// ---------------- conv GEMM: xc = silu( sum_{k,i} xz_shift * conv_w[k,i,o] + b ) ----------
__global__ void __launch_bounds__(256)
gemm_conv(const float* __restrict__ xz, const float* __restrict__ cw,
          const float* __restrict__ cb)
{
    __shared__ float As[8][128];
    __shared__ float Bs[8][128];
    const int t  = threadIdx.x;
    const int n0 = blockIdx.x * 128;
    const int m0 = blockIdx.y * 128;
    const int ar = t >> 1;
    const int ak = (t & 1) * 4;
    const int m  = m0 + ar;
    const int bidx = m >> 10;
    const int l  = m & 1023;
    const int br = t >> 5;
    const int bn = (t & 31) * 4;
    const int tx = t & 15, ty = t >> 4;

    float acc[8][8];
    #pragma unroll
    for (int i = 0; i < 8; i++)
        #pragma unroll
        for (int j = 0; j < 8; j++) acc[i][j] = 0.f;

    // virtual-A loader: A[m, k*2048+i] = xz[b, l+k-3, i] (causal, zero-pad)
    auto loadA = [&](int kt) -> float4 {
        const int k0  = kt << 3;
        const int tap = k0 >> 11;
        const int i0  = k0 & 2047;
        const int ls  = l + tap - 3;
        if (ls < 0) return make_float4(0.f,0.f,0.f,0.f);
        return *(const float4*)(xz + (size_t)((bidx<<10)+ls)*4096 + i0 + ak);
    };
    auto loadB = [&](int kt) -> float4 {
        const int k0 = kt << 3;
        return *(const float4*)(cw + (size_t)(k0+br)*2048 + n0 + bn);
    };

    float4 pa = loadA(0), pb = loadB(0);
    for (int kt = 0; kt < 1024; ++kt) {
        As[ak+0][ar]=pa.x; As[ak+1][ar]=pa.y; As[ak+2][ar]=pa.z; As[ak+3][ar]=pa.w;
        *(float4*)&Bs[br][bn] = pb;
        __syncthreads();
        if (kt + 1 < 1024) { pa = loadA(kt+1); pb = loadB(kt+1); }
        #pragma unroll
        for (int kk = 0; kk < 8; kk++) {
            float a[8], b[8];
            *(float4*)&a[0] = *(const float4*)&As[kk][ty*8];
            *(float4*)&a[4] = *(const float4*)&As[kk][ty*8+4];
            *(float4*)&b[0] = *(const float4*)&Bs[kk][tx*8];
            *(float4*)&b[4] = *(const float4*)&Bs[kk][tx*8+4];
            #pragma unroll
            for (int i = 0; i < 8; i++)
                #pragma unroll
                for (int j = 0; j < 8; j++)
                    acc[i][j] = fmaf(a[i], b[j], acc[i][j]);
        }
        __syncthreads();
    }

    #pragma unroll
    for (int i = 0; i < 8; i++) {
        const int mr = m0 + ty*8 + i;
        #pragma unroll
        for (int j = 0; j < 8; j++) {
            const int n = n0 + tx*8 + j;
            float v = acc[i][j] + cb[n];
            v = v / (1.f + __expf(-v));     // silu
            d_xc[(size_t)mr*Hsz + n] = v;
        }
    }
}

__global__ void reduce_dbc() {
    int i = blockIdx.x*256 + threadIdx.x;
    if (i < Msz*96) {
        float s = 0.f;
        #pragma unroll
        for (int z = 0; z < DBC_SPLITS; z++) s += d_dbcp[(size_t)z*Msz*96 + i];
        d_dbc[i] = s;
    }
}

// ---------------- chunked selective scan (3 passes) ----------------
// pass1: per (b,chunk,h) local scan from 0; record P = prod(decay), S = local final state
__global__ void __launch_bounds__(128) scan_pass1() {
    __shared__ float sB[CHUNK][NST];
    const int bid = blockIdx.x;
    const int ht = bid & 15;
    const int c  = (bid >> 4) & 7;
    const int b  = bid >> 7;
    const int h  = ht*128 + threadIdx.x;
    const int mbase = b*Lsz + c*CHUNK;

    for (int j = threadIdx.x; j < CHUNK*NST; j += 128) {
        int l = j >> 4, n = j & 15;
        sB[l][n] = d_dbc[(size_t)(mbase+l)*96 + 64 + n];
    }
    __syncthreads();

    float a[NST], p[NST], s[NST];
    #pragma unroll
    for (int n = 0; n < NST; n++) { a[n] = d_Aexp[h*NST + n]; p[n] = 1.f; s[n] = 0.f; }

    float dl = d_delta[(size_t)mbase*Hsz + h];
    float xv = d_xc[(size_t)mbase*Hsz + h];
    for (int l = 0; l < CHUNK; l++) {
        float dln = 0.f, xvn = 0.f;
        if (l + 1 < CHUNK) {
            dln = d_delta[(size_t)(mbase+l+1)*Hsz + h];
            xvn = d_xc[(size_t)(mbase+l+1)*Hsz + h];
        }
        const float du = dl * xv;
        #pragma unroll
        for (int n = 0; n < NST; n++) {
            float r = __expf(dl * a[n]);
            p[n] *= r;
            s[n] = fmaf(r, s[n], du * sB[l][n]);
        }
        dl = dln; xv = xvn;
    }
    size_t base = ((size_t)(b*NCHUNK + c)*Hsz + h)*NST;
    #pragma unroll
    for (int n = 0; n < NST; n++) { d_P[base+n] = p[n]; d_S[base+n] = s[n]; }
}

// pass2: sequential combine across chunks -> init state per chunk
__global__ void scan_pass2() {
    int idx = blockIdx.x*256 + threadIdx.x;          // over Bsz*Hsz*NST
    if (idx >= Bsz*Hsz*NST) return;
    int b  = idx / (Hsz*NST);
    int hn = idx % (Hsz*NST);
    float st = 0.f;
    for (int c = 0; c < NCHUNK; c++) {
        size_t o = (size_t)(b*NCHUNK + c)*Hsz*NST + hn;
        d_I[o] = st;
        st = d_P[o]*st + d_S[o];
    }
}

// pass3: rescan with correct init state; emit g = (sum_n s*C + D*xc) * silu(z)
__global__ void __launch_bounds__(128) scan_pass3(const float* __restrict__ Din) {
    __shared__ float sBC[CHUNK][2*NST];
    const int bid = blockIdx.x;
    const int ht = bid & 15;
    const int c  = (bid >> 4) & 7;
    const int b  = bid >> 7;
    const int h  = ht*128 + threadIdx.x;
    const int mbase = b*Lsz + c*CHUNK;

    for (int j = threadIdx.x; j < CHUNK*2*NST; j += 128) {
        int l = j >> 5, cc = j & 31;
        sBC[l][cc] = d_dbc[(size_t)(mbase+l)*96 + 64 + cc];
    }
    __syncthreads();

    float a[NST], s[NST];
    size_t base = ((size_t)(b*NCHUNK + c)*Hsz + h)*NST;
    #pragma unroll
    for (int n = 0; n < NST; n++) { a[n] = d_Aexp[h*NST + n]; s[n] = d_I[base+n]; }
    const float Dh = Din[h];

    float dl = d_delta[(size_t)mbase*Hsz + h];
    float xv = d_xc[(size_t)mbase*Hsz + h];
    for (int l = 0; l < CHUNK; l++) {
        float dln = 0.f, xvn = 0.f;
        if (l + 1 < CHUNK) {
            dln = d_delta[(size_t)(mbase+l+1)*Hsz + h];
            xvn = d_xc[(size_t)(mbase+l+1)*Hsz + h];
        }
        const float du = dl * xv;
        float y = 0.f;
        #pragma unroll
        for (int n = 0; n < NST; n++) {
            float r = __expf(dl * a[n]);
            s[n] = fmaf(r, s[n], du * sBC[l][n]);
            y = fmaf(s[n], sBC[l][NST+n], y);
        }
        y = fmaf(Dh, xv, y);
        const int m = mbase + l;
        float z = d_xz[(size_t)m*4096 + 2048 + h];
        float sz = z / (1.f + __expf(-z));
        d_g[(size_t)m*Hsz + h] = y * sz;
        dl = dln; xv = xvn;
    }
}

// ---------------- launch ----------------
extern "C" void kernel_launch(void* const* d_in, const int* in_sizes, int n_in,
                              void* d_out, int out_size) {
    const float* x          = (const float*)d_in[0];
    const float* norm_w     = (const float*)d_in[1];
    const float* in_proj_w  = (const float*)d_in[2];
    const float* conv_w     = (const float*)d_in[3];
    const float* conv_b     = (const float*)d_in[4];
    const float* x_proj_w   = (const float*)d_in[5];
    const float* dt_proj_w  = (const float*)d_in[6];
    const float* dt_proj_b  = (const float*)d_in[7];
    const float* A_log      = (const float*)d_in[8];
    const float* Dv         = (const float*)d_in[9];
    const float* out_proj_w = (const float*)d_in[10];
    float* out = (float*)d_out;

    float *p_h, *p_xz, *p_xc, *p_dbc, *p_dbcp, *p_delta, *p_g;
    cudaGetSymbolAddress((void**)&p_h, d_h);
    cudaGetSymbolAddress((void**)&p_xz, d_xz);
    cudaGetSymbolAddress((void**)&p_xc, d_xc);
    cudaGetSymbolAddress((void**)&p_dbc, d_dbc);
    cudaGetSymbolAddress((void**)&p_dbcp, d_dbcp);
    cudaGetSymbolAddress((void**)&p_delta, d_delta);
    cudaGetSymbolAddress((void**)&p_g, d_g);

    // 1. rmsnorm + A = -exp(A_log)
    rmsnorm_kernel<<<Msz, 256>>>(x, norm_w);
    aexp_kernel<<<(Hsz*NST + 255)/256, 256>>>(A_log);
    // 2. xz = h @ in_proj_w.T   (M=2048, N=4096, K=2048)
    gemm_wt<0><<<dim3(32,16,1), 256>>>(p_h, in_proj_w, p_xz,
                                       Msz, 2*Hsz, Hsz, Hsz, Hsz, 2*Hsz, nullptr, nullptr);
    // 3. xc = silu(causal dense conv(xz[:, :H]) + b)   (K=8192 virtual)
    gemm_conv<<<dim3(16,16,1), 256>>>(p_xz, conv_w, conv_b);
    // 4. dBC = xc @ x_proj_w.T  (N=96, split-K=8, deterministic reduce)
    gemm_wt<4><<<dim3(1,16,DBC_SPLITS), 256>>>(p_xc, x_proj_w, p_dbcp,
                                               Msz, 96, Hsz, Hsz, Hsz, 96, nullptr, nullptr);
    reduce_dbc<<<(Msz*96 + 255)/256, 256>>>();
    // 5. delta = softplus(dBC[:, :64] @ dt_proj_w.T + b)
    gemm_wt<2><<<dim3(16,16,1), 256>>>(p_dbc, dt_proj_w, p_delta,
                                       Msz, Hsz, 64, 96, 64, Hsz, dt_proj_b, nullptr);
    // 6. chunked selective scan -> g = y * silu(z)
    scan_pass1<<<Bsz*NCHUNK*(Hsz/128), 128>>>();
    scan_pass2<<<(Bsz*Hsz*NST + 255)/256, 256>>>();
    scan_pass3<<<Bsz*NCHUNK*(Hsz/128), 128>>>(Dv);
    // 7. out = x + g @ out_proj_w.T
    gemm_wt<3><<<dim3(16,16,1), 256>>>(p_g, out_proj_w, out,
                                       Msz, Hsz, Hsz, Hsz, Hsz, Hsz, nullptr, x);
}

// round 2
// speedup vs baseline: 2.4557x; 2.4557x over previous
#include <cuda_runtime.h>
#include <math.h>

#define Bsz 2
#define Lsz 1024
#define Hsz 2048
#define Msz (Bsz*Lsz)          // 2048 rows
#define NST 16
#define DTR 64
#define CHUNK 128
#define NCHUNK (Lsz/CHUNK)     // 8
#define DBC_SPLITS 8

// ---------------- scratch (device globals; no runtime allocation) ----------------
__device__ float d_h[(size_t)Msz*Hsz];         // rmsnorm out
__device__ float d_xz[(size_t)Msz*2*Hsz];      // in_proj out (xc_pre | z)
__device__ float d_xc[(size_t)Msz*Hsz];        // conv+silu out
__device__ float d_dbc[(size_t)Msz*96];        // x_proj out
__device__ float d_dbcp[(size_t)DBC_SPLITS*Msz*96];
__device__ float d_delta[(size_t)Msz*Hsz];     // softplus(dt) out
__device__ float d_g[(size_t)Msz*Hsz];         // y * silu(z)
__device__ float d_Aexp[Hsz*NST];              // -exp(A_log)
__device__ float d_P[(size_t)Bsz*NCHUNK*Hsz*NST];  // chunk decay products
__device__ float d_S[(size_t)Bsz*NCHUNK*Hsz*NST];  // chunk local final states
__device__ float d_I[(size_t)Bsz*NCHUNK*Hsz*NST];  // chunk init states

// ---------------- tf32 helpers ----------------
__device__ __forceinline__ unsigned f2tf(float x){
    unsigned y; asm("cvt.rna.tf32.f32 %0, %1;" : "=r"(y) : "f"(x)); return y;
}
__device__ __forceinline__ void mma8(float* c, const unsigned* a, const unsigned* b){
    asm volatile("mma.sync.aligned.m16n8k8.row.col.f32.tf32.tf32.f32 "
      "{%0,%1,%2,%3}, {%4,%5,%6,%7}, {%8,%9}, {%0,%1,%2,%3};"
      : "+f"(c[0]), "+f"(c[1]), "+f"(c[2]), "+f"(c[3])
      : "r"(a[0]), "r"(a[1]), "r"(a[2]), "r"(a[3]), "r"(b[0]), "r"(b[1]));
}

// ---------------- small kernels ----------------
__global__ void aexp_kernel(const float* __restrict__ alog) {
    int i = blockIdx.x*256 + threadIdx.x;
    if (i < Hsz*NST) d_Aexp[i] = -expf(alog[i]);
}

__global__ void rmsnorm_kernel(const float* __restrict__ x, const float* __restrict__ w) {
    const int m = blockIdx.x;
    const float* xr = x + (size_t)m*Hsz;
    float ss = 0.f;
    for (int i = threadIdx.x*4; i < Hsz; i += 1024) {
        float4 v = *(const float4*)(xr + i);
        ss += v.x*v.x + v.y*v.y + v.z*v.z + v.w*v.w;
    }
    __shared__ float red[8];
    #pragma unroll
    for (int o = 16; o; o >>= 1) ss += __shfl_xor_sync(0xffffffffu, ss, o);
    if ((threadIdx.x & 31) == 0) red[threadIdx.x >> 5] = ss;
    __syncthreads();
    if (threadIdx.x == 0) {
        float v = 0.f;
        #pragma unroll
        for (int j = 0; j < 8; j++) v += red[j];
        red[0] = rsqrtf(v * (1.0f/Hsz) + 1e-5f);
    }
    __syncthreads();
    const float sc = red[0];
    float* hr = d_h + (size_t)m*Hsz;
    for (int i = threadIdx.x*4; i < Hsz; i += 1024) {
        float4 v = *(const float4*)(xr + i);
        float4 wv = *(const float4*)(w + i);
        v.x *= sc*wv.x; v.y *= sc*wv.y; v.z *= sc*wv.z; v.w *= sc*wv.w;
        *(float4*)(hr + i) = v;
    }
}

// ================= tensor-core GEMM: C = A(M,K;lda) * W(N,K;ldb)^T =================
// EPI 0: plain; 2: softplus(acc+bias); 3: acc+resid; 4: split-K partial (n<N guard)
template<int EPI>
__global__ void __launch_bounds__(256)
gemm_tc(const float* __restrict__ A, const float* __restrict__ W,
        float* __restrict__ C, int M, int N, int K,
        int lda, int ldb, int ldc,
        const float* __restrict__ bias, const float* __restrict__ resid)
{
    __shared__ unsigned As[128][36];   // As[m][k], pad->conflict-free frag loads
    __shared__ unsigned Bs[128][36];   // Bs[n][k]
    const int t = threadIdx.x;
    const int lane = t & 31;
    const int gid = lane >> 2, tig = lane & 3;
    const int warp = t >> 5;
    const int wm = (warp >> 1) * 32;   // 4 warps along M
    const int wn = (warp & 1) * 64;    // 2 warps along N
    const int n0 = blockIdx.x * 128;
    const int m0 = blockIdx.y * 128;
    const int kslice = K / gridDim.z;
    const int kbeg = blockIdx.z * kslice;
    const int KT = kslice >> 5;

    float* Cb = C;
    if (EPI == 4) Cb += (size_t)blockIdx.z * M * ldc;

    float acc[2][8][4];
    #pragma unroll
    for (int mi = 0; mi < 2; mi++)
        #pragma unroll
        for (int ni = 0; ni < 8; ni++)
            #pragma unroll
            for (int q = 0; q < 4; q++) acc[mi][ni][q] = 0.f;

    int r_[4], kc_[4];
    const float *ApT[4], *BpT[4];
    bool bok[4];
    #pragma unroll
    for (int i = 0; i < 4; i++) {
        int lin = t + i*256;
        r_[i]  = lin >> 3;
        kc_[i] = (lin & 7) * 4;
        ApT[i] = A + (size_t)(m0 + r_[i])*lda + kbeg + kc_[i];
        bok[i] = (n0 + r_[i]) < N;
        BpT[i] = W + (size_t)(n0 + r_[i])*ldb + kbeg + kc_[i];
    }

    float4 pa[4], pb[4];
    #pragma unroll
    for (int i = 0; i < 4; i++) {
        pa[i] = *(const float4*)ApT[i];
        pb[i] = bok[i] ? *(const float4*)BpT[i] : make_float4(0.f,0.f,0.f,0.f);
    }

    for (int kt = 0; kt < KT; kt++) {
        #pragma unroll
        for (int i = 0; i < 4; i++) {
            uint4 ua = make_uint4(f2tf(pa[i].x), f2tf(pa[i].y), f2tf(pa[i].z), f2tf(pa[i].w));
            *(uint4*)&As[r_[i]][kc_[i]] = ua;
            uint4 ub = make_uint4(f2tf(pb[i].x), f2tf(pb[i].y), f2tf(pb[i].z), f2tf(pb[i].w));
            *(uint4*)&Bs[r_[i]][kc_[i]] = ub;
        }
        __syncthreads();
        if (kt + 1 < KT) {
            #pragma unroll
            for (int i = 0; i < 4; i++) {
                pa[i] = *(const float4*)(ApT[i] + (size_t)(kt+1)*32);
                pb[i] = bok[i] ? *(const float4*)(BpT[i] + (size_t)(kt+1)*32)
                               : make_float4(0.f,0.f,0.f,0.f);
            }
        }
        #pragma unroll
        for (int kk = 0; kk < 4; kk++) {
            const int k = kk*8 + tig;
            unsigned a[2][4], b[8][2];
            #pragma unroll
            for (int mi = 0; mi < 2; mi++) {
                int r = wm + mi*16 + gid;
                a[mi][0] = As[r  ][k];
                a[mi][1] = As[r+8][k];
                a[mi][2] = As[r  ][k+4];
                a[mi][3] = As[r+8][k+4];
            }
            #pragma unroll
            for (int ni = 0; ni < 8; ni++) {
                int n = wn + ni*8 + gid;
                b[ni][0] = Bs[n][k];
                b[ni][1] = Bs[n][k+4];
            }
            #pragma unroll
            for (int mi = 0; mi < 2; mi++)
                #pragma unroll
                for (int ni = 0; ni < 8; ni++)
                    mma8(acc[mi][ni], a[mi], b[ni]);
        }
        __syncthreads();
    }

    #pragma unroll
    for (int mi = 0; mi < 2; mi++) {
        #pragma unroll
        for (int rr = 0; rr < 2; rr++) {
            const int m = m0 + wm + mi*16 + rr*8 + gid;
            #pragma unroll
            for (int ni = 0; ni < 8; ni++) {
                const int n = n0 + wn + ni*8 + tig*2;
                if (EPI == 4 && n >= N) continue;
                float v0 = acc[mi][ni][rr*2+0];
                float v1 = acc[mi][ni][rr*2+1];
                if (EPI == 2) {
                    v0 += bias[n];   v0 = (v0 > 20.f) ? v0 : log1pf(__expf(v0));
                    v1 += bias[n+1]; v1 = (v1 > 20.f) ? v1 : log1pf(__expf(v1));
                }
                if (EPI == 3) {
                    v0 += resid[(size_t)m*ldc + n];
                    v1 += resid[(size_t)m*ldc + n + 1];
                }
                *(float2*)&Cb[(size_t)m*ldc + n] = make_float2(v0, v1);
            }
        }
    }
}

// ============ conv as tensor-core GEMM (K=8192 virtual over 4 taps) ============
__global__ void __launch_bounds__(256)
gemm_conv_tc(const float* __restrict__ xz, const float* __restrict__ cw,
             const float* __restrict__ cb)
{
    __shared__ unsigned As[128][36];   // As[m][k]
    __shared__ unsigned Bs[32][132];   // Bs[k][n] (conv_w is K-major already)
    const int t = threadIdx.x;
    const int lane = t & 31;
    const int gid = lane >> 2, tig = lane & 3;
    const int warp = t >> 5;
    const int wm = (warp >> 1) * 32;
    const int wn = (warp & 1) * 64;
    const int n0 = blockIdx.x * 128;
    const int m0 = blockIdx.y * 128;

    float acc[2][8][4];
    #pragma unroll
    for (int mi = 0; mi < 2; mi++)
        #pragma unroll
        for (int ni = 0; ni < 8; ni++)
            #pragma unroll
            for (int q = 0; q < 4; q++) acc[mi][ni][q] = 0.f;

    int rA[4], kcA[4], krB[4], ncB[4];
    #pragma unroll
    for (int i = 0; i < 4; i++) {
        int lin = t + i*256;
        rA[i]  = lin >> 3;  kcA[i] = (lin & 7) * 4;
        krB[i] = lin >> 5;  ncB[i] = (lin & 31) * 4;
    }

    auto loadA = [&](int kt, int i) -> float4 {
        const int tap = kt >> 6;               // 32k per tile, 2048 per tap
        const int i0  = (kt & 63) * 32;
        const int m   = m0 + rA[i];
        const int b   = m >> 10;
        const int l   = m & 1023;
        const int ls  = l + tap - 3;
        if (ls < 0) return make_float4(0.f,0.f,0.f,0.f);
        return *(const float4*)(xz + (size_t)((b<<10)+ls)*4096 + i0 + kcA[i]);
    };
    auto loadB = [&](int kt, int i) -> float4 {
        return *(const float4*)(cw + (size_t)(kt*32 + krB[i])*2048 + n0 + ncB[i]);
    };

    float4 pa[4], pb[4];
    #pragma unroll
    for (int i = 0; i < 4; i++) { pa[i] = loadA(0, i); pb[i] = loadB(0, i); }

    for (int kt = 0; kt < 256; kt++) {
        #pragma unroll
        for (int i = 0; i < 4; i++) {
            uint4 ua = make_uint4(f2tf(pa[i].x), f2tf(pa[i].y), f2tf(pa[i].z), f2tf(pa[i].w));
            *(uint4*)&As[rA[i]][kcA[i]] = ua;
            uint4 ub = make_uint4(f2tf(pb[i].x), f2tf(pb[i].y), f2tf(pb[i].z), f2tf(pb[i].w));
            *(uint4*)&Bs[krB[i]][ncB[i]] = ub;
        }
        __syncthreads();
        if (kt + 1 < 256) {
            #pragma unroll
            for (int i = 0; i < 4; i++) { pa[i] = loadA(kt+1, i); pb[i] = loadB(kt+1, i); }
        }
        #pragma unroll
        for (int kk = 0; kk < 4; kk++) {
            const int k = kk*8 + tig;
            unsigned a[2][4], b[8][2];
            #pragma unroll
            for (int mi = 0; mi < 2; mi++) {
                int r = wm + mi*16 + gid;
                a[mi][0] = As[r  ][k];
                a[mi][1] = As[r+8][k];
                a[mi][2] = As[r  ][k+4];
                a[mi][3] = As[r+8][k+4];
            }
            #pragma unroll
            for (int ni = 0; ni < 8; ni++) {
                int n = wn + ni*8 + gid;
                b[ni][0] = Bs[k  ][n];
                b[ni][1] = Bs[k+4][n];
            }
            #pragma unroll
            for (int mi = 0; mi < 2; mi++)
                #pragma unroll
                for (int ni = 0; ni < 8; ni++)
                    mma8(acc[mi][ni], a[mi], b[ni]);
        }
        __syncthreads();
    }

    #pragma unroll
    for (int mi = 0; mi < 2; mi++) {
        #pragma unroll
        for (int rr = 0; rr < 2; rr++) {
            const int m = m0 + wm + mi*16 + rr*8 + gid;
            #pragma unroll
            for (int ni = 0; ni < 8; ni++) {
                const int n = n0 + wn + ni*8 + tig*2;
                float v0 = acc[mi][ni][rr*2+0] + cb[n];
                float v1 = acc[mi][ni][rr*2+1] + cb[n+1];
                v0 = v0 / (1.f + __expf(-v0));
                v1 = v1 / (1.f + __expf(-v1));
                *(float2*)&d_xc[(size_t)m*Hsz + n] = make_float2(v0, v1);
            }
        }
    }
}

__global__ void reduce_dbc() {
    int i = blockIdx.x*256 + threadIdx.x;
    if (i < Msz*96) {
        float s = 0.f;
        #pragma unroll
        for (int z = 0; z < DBC_SPLITS; z++) s += d_dbcp[(size_t)z*Msz*96 + i];
        d_dbc[i] = s;
    }
}

// ---------------- chunked selective scan (3 passes) ----------------
__global__ void __launch_bounds__(128) scan_pass1() {
    __shared__ float sB[CHUNK][NST];
    const int bid = blockIdx.x;
    const int ht = bid & 15;
    const int c  = (bid >> 4) & 7;
    const int b  = bid >> 7;
    const int h  = ht*128 + threadIdx.x;
    const int mbase = b*Lsz + c*CHUNK;

    for (int j = threadIdx.x; j < CHUNK*NST; j += 128) {
        int l = j >> 4, n = j & 15;
        sB[l][n] = d_dbc[(size_t)(mbase+l)*96 + 64 + n];
    }
    __syncthreads();

    float a[NST], p[NST], s[NST];
    #pragma unroll
    for (int n = 0; n < NST; n++) { a[n] = d_Aexp[h*NST + n]; p[n] = 1.f; s[n] = 0.f; }

    float dl = d_delta[(size_t)mbase*Hsz + h];
    float xv = d_xc[(size_t)mbase*Hsz + h];
    for (int l = 0; l < CHUNK; l++) {
        float dln = 0.f, xvn = 0.f;
        if (l + 1 < CHUNK) {
            dln = d_delta[(size_t)(mbase+l+1)*Hsz + h];
            xvn = d_xc[(size_t)(mbase+l+1)*Hsz + h];
        }
        const float du = dl * xv;
        #pragma unroll
        for (int n = 0; n < NST; n++) {
            float r = __expf(dl * a[n]);
            p[n] *= r;
            s[n] = fmaf(r, s[n], du * sB[l][n]);
        }
        dl = dln; xv = xvn;
    }
    size_t base = ((size_t)(b*NCHUNK + c)*Hsz + h)*NST;
    #pragma unroll
    for (int n = 0; n < NST; n++) { d_P[base+n] = p[n]; d_S[base+n] = s[n]; }
}

__global__ void scan_pass2() {
    int idx = blockIdx.x*256 + threadIdx.x;
    if (idx >= Bsz*Hsz*NST) return;
    int b  = idx / (Hsz*NST);
    int hn = idx % (Hsz*NST);
    float st = 0.f;
    for (int c = 0; c < NCHUNK; c++) {
        size_t o = (size_t)(b*NCHUNK + c)*Hsz*NST + hn;
        d_I[o] = st;
        st = d_P[o]*st + d_S[o];
    }
}

__global__ void __launch_bounds__(128) scan_pass3(const float* __restrict__ Din) {
    __shared__ float sBC[CHUNK][2*NST];
    const int bid = blockIdx.x;
    const int ht = bid & 15;
    const int c  = (bid >> 4) & 7;
    const int b  = bid >> 7;
    const int h  = ht*128 + threadIdx.x;
    const int mbase = b*Lsz + c*CHUNK;

    for (int j = threadIdx.x; j < CHUNK*2*NST; j += 128) {
        int l = j >> 5, cc = j & 31;
        sBC[l][cc] = d_dbc[(size_t)(mbase+l)*96 + 64 + cc];
    }
    __syncthreads();

    float a[NST], s[NST];
    size_t base = ((size_t)(b*NCHUNK + c)*Hsz + h)*NST;
    #pragma unroll
    for (int n = 0; n < NST; n++) { a[n] = d_Aexp[h*NST + n]; s[n] = d_I[base+n]; }
    const float Dh = Din[h];

    float dl = d_delta[(size_t)mbase*Hsz + h];
    float xv = d_xc[(size_t)mbase*Hsz + h];
    for (int l = 0; l < CHUNK; l++) {
        float dln = 0.f, xvn = 0.f;
        if (l + 1 < CHUNK) {
            dln = d_delta[(size_t)(mbase+l+1)*Hsz + h];
            xvn = d_xc[(size_t)(mbase+l+1)*Hsz + h];
        }
        const float du = dl * xv;
        float y = 0.f;
        #pragma unroll
        for (int n = 0; n < NST; n++) {
            float r = __expf(dl * a[n]);
            s[n] = fmaf(r, s[n], du * sBC[l][n]);
            y = fmaf(s[n], sBC[l][NST+n], y);
        }
        y = fmaf(Dh, xv, y);
        const int m = mbase + l;
        float z = d_xz[(size_t)m*4096 + 2048 + h];
        float sz = z / (1.f + __expf(-z));
        d_g[(size_t)m*Hsz + h] = y * sz;
        dl = dln; xv = xvn;
    }
}

// ---------------- launch ----------------
extern "C" void kernel_launch(void* const* d_in, const int* in_sizes, int n_in,
                              void* d_out, int out_size) {
    const float* x          = (const float*)d_in[0];
    const float* norm_w     = (const float*)d_in[1];
    const float* in_proj_w  = (const float*)d_in[2];
    const float* conv_w     = (const float*)d_in[3];
    const float* conv_b     = (const float*)d_in[4];
    const float* x_proj_w   = (const float*)d_in[5];
    const float* dt_proj_w  = (const float*)d_in[6];
    const float* dt_proj_b  = (const float*)d_in[7];
    const float* A_log      = (const float*)d_in[8];
    const float* Dv         = (const float*)d_in[9];
    const float* out_proj_w = (const float*)d_in[10];
    float* out = (float*)d_out;

    float *p_h, *p_xz, *p_xc, *p_dbc, *p_dbcp, *p_delta, *p_g;
    cudaGetSymbolAddress((void**)&p_h, d_h);
    cudaGetSymbolAddress((void**)&p_xz, d_xz);
    cudaGetSymbolAddress((void**)&p_xc, d_xc);
    cudaGetSymbolAddress((void**)&p_dbc, d_dbc);
    cudaGetSymbolAddress((void**)&p_dbcp, d_dbcp);
    cudaGetSymbolAddress((void**)&p_delta, d_delta);
    cudaGetSymbolAddress((void**)&p_g, d_g);

    // 1. rmsnorm + A = -exp(A_log)
    rmsnorm_kernel<<<Msz, 256>>>(x, norm_w);
    aexp_kernel<<<(Hsz*NST + 255)/256, 256>>>(A_log);
    // 2. xz = h @ in_proj_w.T   (M=2048, N=4096, K=2048)
    gemm_tc<0><<<dim3(32,16,1), 256>>>(p_h, in_proj_w, p_xz,
                                       Msz, 2*Hsz, Hsz, Hsz, Hsz, 2*Hsz, nullptr, nullptr);
    // 3. xc = silu(causal dense conv(xz[:, :H]) + b)   (K=8192 virtual)
    gemm_conv_tc<<<dim3(16,16,1), 256>>>(p_xz, conv_w, conv_b);
    // 4. dBC = xc @ x_proj_w.T  (N=96, split-K=8, deterministic reduce)
    gemm_tc<4><<<dim3(1,16,DBC_SPLITS), 256>>>(p_xc, x_proj_w, p_dbcp,
                                               Msz, 96, Hsz, Hsz, Hsz, 96, nullptr, nullptr);
    reduce_dbc<<<(Msz*96 + 255)/256, 256>>>();
    // 5. delta = softplus(dBC[:, :64] @ dt_proj_w.T + b)
    gemm_tc<2><<<dim3(16,16,1), 256>>>(p_dbc, dt_proj_w, p_delta,
                                       Msz, Hsz, 64, 96, 64, Hsz, dt_proj_b, nullptr);
    // 6. chunked selective scan -> g = y * silu(z)
    scan_pass1<<<Bsz*NCHUNK*(Hsz/128), 128>>>();
    scan_pass2<<<(Bsz*Hsz*NST + 255)/256, 256>>>();
    scan_pass3<<<Bsz*NCHUNK*(Hsz/128), 128>>>(Dv);
    // 7. out = x + g @ out_proj_w.T
    gemm_tc<3><<<dim3(16,16,1), 256>>>(p_g, out_proj_w, out,
                                       Msz, Hsz, Hsz, Hsz, Hsz, Hsz, nullptr, x);
}

// round 4
// speedup vs baseline: 2.8522x; 1.1614x over previous
#include <cuda_runtime.h>
#include <math.h>
#include <stdint.h>

#define Bsz 2
#define Lsz 1024
#define Hsz 2048
#define Msz (Bsz*Lsz)          // 2048 rows
#define NST 16
#define CHUNK 128
#define NCHUNK (Lsz/CHUNK)     // 8
#define DBC_SPLITS 8

// tc gemm tile
#define TM 128
#define TN 256
#define KC 32
#define SB_OFF (128*36)                      // unsigned units
#define SMEM_TOT ((128*36 + 256*36)*4)       // 55296 bytes

// ---------------- scratch ----------------
__device__ float d_h[(size_t)Msz*Hsz];
__device__ float d_xz[(size_t)Msz*2*Hsz];
__device__ float d_xc[(size_t)Msz*Hsz];
__device__ float d_dbc[(size_t)Msz*96];
__device__ float d_dbcp[(size_t)DBC_SPLITS*Msz*96];
__device__ float d_delta[(size_t)Msz*Hsz];
__device__ float d_g[(size_t)Msz*Hsz];
__device__ float d_Aexp[Hsz*NST];
__device__ float d_P[(size_t)Bsz*NCHUNK*Hsz*NST];
__device__ float d_S[(size_t)Bsz*NCHUNK*Hsz*NST];
__device__ float d_I[(size_t)Bsz*NCHUNK*Hsz*NST];
__device__ float d_cwT[(size_t)Hsz*4*Hsz];   // conv_w transposed [n][k=8192]

// ---------------- helpers ----------------
__device__ __forceinline__ unsigned f2tf(float x){
    unsigned y; asm("cvt.rna.tf32.f32 %0, %1;" : "=r"(y) : "f"(x)); return y;
}
__device__ __forceinline__ void mma8(float* c, const unsigned* a, const unsigned* b){
    asm volatile("mma.sync.aligned.m16n8k8.row.col.f32.tf32.tf32.f32 "
      "{%0,%1,%2,%3}, {%4,%5,%6,%7}, {%8,%9}, {%0,%1,%2,%3};"
      : "+f"(c[0]), "+f"(c[1]), "+f"(c[2]), "+f"(c[3])
      : "r"(a[0]), "r"(a[1]), "r"(a[2]), "r"(a[3]), "r"(b[0]), "r"(b[1]));
}
__device__ __forceinline__ void ldsm4(unsigned* r, uint32_t a){
    asm volatile("ldmatrix.sync.aligned.m8n8.x4.shared.b16 {%0,%1,%2,%3}, [%4];"
        : "=r"(r[0]), "=r"(r[1]), "=r"(r[2]), "=r"(r[3]) : "r"(a));
}
__device__ __forceinline__ uint32_t smem_u32(const void* p){
    uint32_t a; asm("{ .reg .u64 t; cvta.to.shared.u64 t, %1; cvt.u32.u64 %0, t; }" : "=r"(a) : "l"(p));
    return a;
}

// ---------------- prep: conv_w [k=8192][n=2048] -> [n][k] ----------------
__global__ void convT(const float* __restrict__ cw){
    __shared__ float tl[32][33];
    const int k0 = blockIdx.x*32, n0 = blockIdx.y*32;
    const int tx = threadIdx.x, ty = threadIdx.y;
    #pragma unroll
    for (int d = 0; d < 4; d++)
        tl[ty + d*8][tx] = cw[(size_t)(k0+ty+d*8)*Hsz + n0 + tx];
    __syncthreads();
    #pragma unroll
    for (int d = 0; d < 4; d++)
        d_cwT[(size_t)(n0+ty+d*8)*(4*Hsz) + k0 + tx] = tl[tx][ty+d*8];
}

// ---------------- small kernels ----------------
__global__ void aexp_kernel(const float* __restrict__ alog) {
    int i = blockIdx.x*256 + threadIdx.x;
    if (i < Hsz*NST) d_Aexp[i] = -expf(alog[i]);
}

__global__ void rmsnorm_kernel(const float* __restrict__ x, const float* __restrict__ w) {
    const int m = blockIdx.x;
    const float* xr = x + (size_t)m*Hsz;
    float ss = 0.f;
    for (int i = threadIdx.x*4; i < Hsz; i += 1024) {
        float4 v = *(const float4*)(xr + i);
        ss += v.x*v.x + v.y*v.y + v.z*v.z + v.w*v.w;
    }
    __shared__ float red[8];
    #pragma unroll
    for (int o = 16; o; o >>= 1) ss += __shfl_xor_sync(0xffffffffu, ss, o);
    if ((threadIdx.x & 31) == 0) red[threadIdx.x >> 5] = ss;
    __syncthreads();
    if (threadIdx.x == 0) {
        float v = 0.f;
        #pragma unroll
        for (int j = 0; j < 8; j++) v += red[j];
        red[0] = rsqrtf(v * (1.0f/Hsz) + 1e-5f);
    }
    __syncthreads();
    const float sc = red[0];
    float* hr = d_h + (size_t)m*Hsz;
    for (int i = threadIdx.x*4; i < Hsz; i += 1024) {
        float4 v = *(const float4*)(xr + i);
        float4 wv = *(const float4*)(w + i);
        v.x *= sc*wv.x; v.y *= sc*wv.y; v.z *= sc*wv.z; v.w *= sc*wv.w;
        *(float4*)(hr + i) = v;
    }
}

// ============ tf32 tensor GEMM: C = A(M,K) * W(N,K)^T, ldmatrix path ============
// block 128x256, 512 thr, warp tile 32x64
// EPI 0: plain; 1: conv bias+silu; 2: resid add
template<int EPI, bool CONVA>
__global__ void __launch_bounds__(512, 1)
gemm_tc(const float* __restrict__ A, const float* __restrict__ W,
        float* __restrict__ C, const float* __restrict__ aux,
        int K, int lda, int ldc)
{
    extern __shared__ __align__(16) unsigned sm[];
    unsigned* As = sm;              // [128][36]
    unsigned* Bs = sm + SB_OFF;     // [256][36]
    const int t = threadIdx.x;
    const int lane = t & 31, w = t >> 5;
    const int gid = lane >> 2, tig = lane & 3;
    const int wm = (w & 3) * 32, wn = (w >> 2) * 64;
    const int n0 = blockIdx.x * TN, m0 = blockIdx.y * TM;

    const int r0 = t >> 3;             // 0..63
    const int kc = (t & 7) * 4;

    const float* Ap = CONVA ? A : (A + (size_t)(m0 + r0)*lda + kc);
    const float* Bp = W + (size_t)(n0 + r0)*K + kc;

    float acc[2][8][4];
    #pragma unroll
    for (int mi = 0; mi < 2; mi++)
        #pragma unroll
        for (int ni = 0; ni < 8; ni++)
            #pragma unroll
            for (int q = 0; q < 4; q++) acc[mi][ni][q] = 0.f;

    // ldmatrix lane addressing
    const int lrow = lane & 15;
    const int lcol = (lane & 16) ? 4 : 0;
    uint32_t a_ad[2], b_ad[4];
    {
        uint32_t sa = smem_u32(As), sb2 = smem_u32(Bs);
        #pragma unroll
        for (int mi = 0; mi < 2; mi++)
            a_ad[mi] = sa + (uint32_t)(((wm + mi*16 + lrow)*36 + lcol) * 4);
        #pragma unroll
        for (int p = 0; p < 4; p++)
            b_ad[p] = sb2 + (uint32_t)(((wn + p*16 + lrow)*36 + lcol) * 4);
    }

    const int nc = K / KC;
    float4 pa[2], pb[4];

    auto loadAB = [&](int kb){
        if (!CONVA) {
            pa[0] = *(const float4*)(Ap + kb);
            pa[1] = *(const float4*)(Ap + (size_t)64*lda + kb);
        } else {
            const int tap = kb >> 11, kin = kb & (Hsz-1);
            #pragma unroll
            for (int i = 0; i < 2; i++) {
                const int m = m0 + r0 + 64*i;
                const int ls = (m & 1023) + tap - 3;
                pa[i] = make_float4(0.f,0.f,0.f,0.f);
                if (ls >= 0)
                    pa[i] = *(const float4*)(A + (size_t)((m & ~1023) + ls)*4096 + kin + kc);
            }
        }
        #pragma unroll
        for (int i = 0; i < 4; i++)
            pb[i] = *(const float4*)(Bp + (size_t)i*64*K + kb);
    };

    loadAB(0);
    for (int c = 0; c < nc; c++) {
        #pragma unroll
        for (int i = 0; i < 2; i++) {
            uint4 u = make_uint4(f2tf(pa[i].x), f2tf(pa[i].y), f2tf(pa[i].z), f2tf(pa[i].w));
            *(uint4*)(As + (r0 + 64*i)*36 + kc) = u;
        }
        #pragma unroll
        for (int i = 0; i < 4; i++) {
            uint4 u = make_uint4(f2tf(pb[i].x), f2tf(pb[i].y), f2tf(pb[i].z), f2tf(pb[i].w));
            *(uint4*)(Bs + (r0 + 64*i)*36 + kc) = u;
        }
        __syncthreads();
        if (c + 1 < nc) loadAB((c+1)*KC);
        #pragma unroll
        for (int kk = 0; kk < 4; kk++) {
            unsigned af[2][4], bf[4][4];
            ldsm4(af[0], a_ad[0] + kk*32);
            ldsm4(af[1], a_ad[1] + kk*32);
            #pragma unroll
            for (int p = 0; p < 4; p++) ldsm4(bf[p], b_ad[p] + kk*32);
            #pragma unroll
            for (int mi = 0; mi < 2; mi++)
                #pragma unroll
                for (int ni = 0; ni < 8; ni++) {
                    unsigned bb[2] = { bf[ni>>1][ni&1], bf[ni>>1][2 + (ni&1)] };
                    mma8(acc[mi][ni], af[mi], bb);
                }
        }
        __syncthreads();
    }

    // epilogue
    #pragma unroll
    for (int mi = 0; mi < 2; mi++) {
        #pragma unroll
        for (int rr = 0; rr < 2; rr++) {
            const int m = m0 + wm + mi*16 + rr*8 + gid;
            #pragma unroll
            for (int ni = 0; ni < 8; ni++) {
                const int n = n0 + wn + ni*8 + tig*2;
                float v0 = acc[mi][ni][rr*2+0];
                float v1 = acc[mi][ni][rr*2+1];
                if (EPI == 1) {
                    v0 += aux[n];   v1 += aux[n+1];
                    v0 = v0 / (1.f + __expf(-v0));
                    v1 = v1 / (1.f + __expf(-v1));
                }
                if (EPI == 2) {
                    v0 += aux[(size_t)m*ldc + n];
                    v1 += aux[(size_t)m*ldc + n + 1];
                }
                *(float2*)&C[(size_t)m*ldc + n] = make_float2(v0, v1);
            }
        }
    }
}

// ---------------- fp32 SIMT GEMM (exact; small ops) ----------------
// EPI 2: softplus(acc+bias); 4: split-K partial (n<N guard)
template<int EPI>
__global__ void __launch_bounds__(256)
gemm_wt(const float* __restrict__ A, const float* __restrict__ W,
        float* __restrict__ C, int M, int N, int K,
        int lda, int ldb, int ldc,
        const float* __restrict__ bias)
{
    __shared__ float As[8][128];
    __shared__ float Bs[8][128];
    const int t  = threadIdx.x;
    const int n0 = blockIdx.x * 128;
    const int m0 = blockIdx.y * 128;
    const int kslice = K / gridDim.z;
    const int kbeg = blockIdx.z * kslice;
    const int KT = kslice >> 3;

    const int ar = t >> 1;
    const int ak = (t & 1) * 4;
    const float* Ap = A + (size_t)(m0 + ar)*lda + kbeg + ak;
    const bool wok = (n0 + ar) < N;
    const float* Wp = W + (size_t)(n0 + ar)*ldb + kbeg + ak;

    float* Cb = C;
    if (EPI == 4) Cb = C + (size_t)blockIdx.z * M * ldc;

    const int tx = t & 15, ty = t >> 4;
    float acc[8][8];
    #pragma unroll
    for (int i = 0; i < 8; i++)
        #pragma unroll
        for (int j = 0; j < 8; j++) acc[i][j] = 0.f;

    float4 pa = *(const float4*)Ap;
    float4 pb = wok ? *(const float4*)Wp : make_float4(0.f,0.f,0.f,0.f);

    for (int kt = 0; kt < KT; ++kt) {
        As[ak+0][ar]=pa.x; As[ak+1][ar]=pa.y; As[ak+2][ar]=pa.z; As[ak+3][ar]=pa.w;
        Bs[ak+0][ar]=pb.x; Bs[ak+1][ar]=pb.y; Bs[ak+2][ar]=pb.z; Bs[ak+3][ar]=pb.w;
        __syncthreads();
        if (kt + 1 < KT) {
            pa = *(const float4*)(Ap + (size_t)(kt+1)*8);
            pb = wok ? *(const float4*)(Wp + (size_t)(kt+1)*8) : make_float4(0.f,0.f,0.f,0.f);
        }
        #pragma unroll
        for (int kk = 0; kk < 8; kk++) {
            float a[8], b[8];
            *(float4*)&a[0] = *(const float4*)&As[kk][ty*8];
            *(float4*)&a[4] = *(const float4*)&As[kk][ty*8+4];
            *(float4*)&b[0] = *(const float4*)&Bs[kk][tx*8];
            *(float4*)&b[4] = *(const float4*)&Bs[kk][tx*8+4];
            #pragma unroll
            for (int i = 0; i < 8; i++)
                #pragma unroll
                for (int j = 0; j < 8; j++)
                    acc[i][j] = fmaf(a[i], b[j], acc[i][j]);
        }
        __syncthreads();
    }

    #pragma unroll
    for (int i = 0; i < 8; i++) {
        const int m = m0 + ty*8 + i;
        #pragma unroll
        for (int j = 0; j < 8; j++) {
            const int n = n0 + tx*8 + j;
            if (n < N) {
                float v = acc[i][j];
                if (EPI == 2) { v += bias[n]; v = (v > 20.f) ? v : log1pf(__expf(v)); }
                Cb[(size_t)m*ldc + n] = v;
            }
        }
    }
}

__global__ void reduce_dbc() {
    int i = blockIdx.x*256 + threadIdx.x;
    if (i < Msz*96) {
        float s = 0.f;
        #pragma unroll
        for (int z = 0; z < DBC_SPLITS; z++) s += d_dbcp[(size_t)z*Msz*96 + i];
        d_dbc[i] = s;
    }
}

// ---------------- chunked selective scan ----------------
__global__ void __launch_bounds__(128) scan_pass1() {
    __shared__ float sB[CHUNK][NST];
    const int bid = blockIdx.x;
    const int ht = bid & 15;
    const int c  = (bid >> 4) & 7;
    const int b  = bid >> 7;
    const int h  = ht*128 + threadIdx.x;
    const int mbase = b*Lsz + c*CHUNK;

    for (int j = threadIdx.x; j < CHUNK*NST; j += 128) {
        int l = j >> 4, n = j & 15;
        sB[l][n] = d_dbc[(size_t)(mbase+l)*96 + 64 + n];
    }
    __syncthreads();

    float a[NST], p[NST], s[NST];
    #pragma unroll
    for (int n = 0; n < NST; n++) { a[n] = d_Aexp[h*NST + n]; p[n] = 1.f; s[n] = 0.f; }

    float dl = d_delta[(size_t)mbase*Hsz + h];
    float xv = d_xc[(size_t)mbase*Hsz + h];
    for (int l = 0; l < CHUNK; l++) {
        float dln = 0.f, xvn = 0.f;
        if (l + 1 < CHUNK) {
            dln = d_delta[(size_t)(mbase+l+1)*Hsz + h];
            xvn = d_xc[(size_t)(mbase+l+1)*Hsz + h];
        }
        const float du = dl * xv;
        #pragma unroll
        for (int n = 0; n < NST; n++) {
            float r = __expf(dl * a[n]);
            p[n] *= r;
            s[n] = fmaf(r, s[n], du * sB[l][n]);
        }
        dl = dln; xv = xvn;
    }
    size_t base = ((size_t)(b*NCHUNK + c)*Hsz + h)*NST;
    #pragma unroll
    for (int n = 0; n < NST; n++) { d_P[base+n] = p[n]; d_S[base+n] = s[n]; }
}

__global__ void scan_pass2() {
    int idx = blockIdx.x*256 + threadIdx.x;
    if (idx >= Bsz*Hsz*NST) return;
    int b  = idx / (Hsz*NST);
    int hn = idx % (Hsz*NST);
    float st = 0.f;
    for (int c = 0; c < NCHUNK; c++) {
        size_t o = (size_t)(b*NCHUNK + c)*Hsz*NST + hn;
        d_I[o] = st;
        st = d_P[o]*st + d_S[o];
    }
}

__global__ void __launch_bounds__(128) scan_pass3(const float* __restrict__ Din) {
    __shared__ float sBC[CHUNK][2*NST];
    const int bid = blockIdx.x;
    const int ht = bid & 15;
    const int c  = (bid >> 4) & 7;
    const int b  = bid >> 7;
    const int h  = ht*128 + threadIdx.x;
    const int mbase = b*Lsz + c*CHUNK;

    for (int j = threadIdx.x; j < CHUNK*2*NST; j += 128) {
        int l = j >> 5, cc = j & 31;
        sBC[l][cc] = d_dbc[(size_t)(mbase+l)*96 + 64 + cc];
    }
    __syncthreads();

    float a[NST], s[NST];
    size_t base = ((size_t)(b*NCHUNK + c)*Hsz + h)*NST;
    #pragma unroll
    for (int n = 0; n < NST; n++) { a[n] = d_Aexp[h*NST + n]; s[n] = d_I[base+n]; }
    const float Dh = Din[h];

    float dl = d_delta[(size_t)mbase*Hsz + h];
    float xv = d_xc[(size_t)mbase*Hsz + h];
    for (int l = 0; l < CHUNK; l++) {
        float dln = 0.f, xvn = 0.f;
        if (l + 1 < CHUNK) {
            dln = d_delta[(size_t)(mbase+l+1)*Hsz + h];
            xvn = d_xc[(size_t)(mbase+l+1)*Hsz + h];
        }
        const float du = dl * xv;
        float y = 0.f;
        #pragma unroll
        for (int n = 0; n < NST; n++) {
            float r = __expf(dl * a[n]);
            s[n] = fmaf(r, s[n], du * sBC[l][n]);
            y = fmaf(s[n], sBC[l][NST+n], y);
        }
        y = fmaf(Dh, xv, y);
        const int m = mbase + l;
        float z = d_xz[(size_t)m*4096 + 2048 + h];
        float sz = z / (1.f + __expf(-z));
        d_g[(size_t)m*Hsz + h] = y * sz;
        dl = dln; xv = xvn;
    }
}

// ---------------- launch ----------------
extern "C" void kernel_launch(void* const* d_in, const int* in_sizes, int n_in,
                              void* d_out, int out_size) {
    const float* x          = (const float*)d_in[0];
    const float* norm_w     = (const float*)d_in[1];
    const float* in_proj_w  = (const float*)d_in[2];
    const float* conv_w     = (const float*)d_in[3];
    const float* conv_b     = (const float*)d_in[4];
    const float* x_proj_w   = (const float*)d_in[5];
    const float* dt_proj_w  = (const float*)d_in[6];
    const float* dt_proj_b  = (const float*)d_in[7];
    const float* A_log      = (const float*)d_in[8];
    const float* Dv         = (const float*)d_in[9];
    const float* out_proj_w = (const float*)d_in[10];
    float* out = (float*)d_out;

    static int attr_done = 0;
    if (!attr_done) {
        cudaFuncSetAttribute(gemm_tc<0,false>, cudaFuncAttributeMaxDynamicSharedMemorySize, SMEM_TOT);
        cudaFuncSetAttribute(gemm_tc<1,true >, cudaFuncAttributeMaxDynamicSharedMemorySize, SMEM_TOT);
        cudaFuncSetAttribute(gemm_tc<2,false>, cudaFuncAttributeMaxDynamicSharedMemorySize, SMEM_TOT);
        attr_done = 1;
    }

    float *p_h, *p_xz, *p_xc, *p_dbc, *p_dbcp, *p_delta, *p_g, *p_cwT;
    cudaGetSymbolAddress((void**)&p_h, d_h);
    cudaGetSymbolAddress((void**)&p_xz, d_xz);
    cudaGetSymbolAddress((void**)&p_xc, d_xc);
    cudaGetSymbolAddress((void**)&p_dbc, d_dbc);
    cudaGetSymbolAddress((void**)&p_dbcp, d_dbcp);
    cudaGetSymbolAddress((void**)&p_delta, d_delta);
    cudaGetSymbolAddress((void**)&p_g, d_g);
    cudaGetSymbolAddress((void**)&p_cwT, d_cwT);

    // 0. prep: conv weight transpose; A = -exp(A_log)
    convT<<<dim3(4*Hsz/32, Hsz/32), dim3(32,8)>>>(conv_w);
    aexp_kernel<<<(Hsz*NST + 255)/256, 256>>>(A_log);
    // 1. rmsnorm
    rmsnorm_kernel<<<Msz, 256>>>(x, norm_w);
    // 2. in_proj: xz = h @ W^T   (M=2048, N=4096, K=2048)
    gemm_tc<0,false><<<dim3(2*Hsz/TN, Msz/TM), 512, SMEM_TOT>>>(
        p_h, in_proj_w, p_xz, nullptr, Hsz, Hsz, 2*Hsz);
    // 3. conv: xc = silu(conv(xz[:, :H]) + b)   (K=8192 virtual)
    gemm_tc<1,true><<<dim3(Hsz/TN, Msz/TM), 512, SMEM_TOT>>>(
        p_xz, p_cwT, p_xc, conv_b, 4*Hsz, 4*Hsz, Hsz);
    // 4. dBC = xc @ x_proj_w.T  (exact fp32, split-K)
    gemm_wt<4><<<dim3(1,16,DBC_SPLITS), 256>>>(p_xc, x_proj_w, p_dbcp,
                                               Msz, 96, Hsz, Hsz, Hsz, 96, nullptr);
    reduce_dbc<<<(Msz*96 + 255)/256, 256>>>();
    // 5. delta = softplus(dBC[:, :64] @ dt_proj_w.T + b)  (exact fp32)
    gemm_wt<2><<<dim3(16,16,1), 256>>>(p_dbc, dt_proj_w, p_delta,
                                       Msz, Hsz, 64, 96, 64, Hsz, dt_proj_b);
    // 6. chunked selective scan -> g = y * silu(z)
    scan_pass1<<<Bsz*NCHUNK*(Hsz/128), 128>>>();
    scan_pass2<<<(Bsz*Hsz*NST + 255)/256, 256>>>();
    scan_pass3<<<Bsz*NCHUNK*(Hsz/128), 128>>>(Dv);
    // 7. out = x + g @ out_proj_w.T
    gemm_tc<2,false><<<dim3(Hsz/TN, Msz/TM), 512, SMEM_TOT>>>(
        p_g, out_proj_w, out, x, Hsz, Hsz, Hsz);
}

// round 5
// speedup vs baseline: 2.8982x; 1.0161x over previous
#include <cuda_runtime.h>
#include <math.h>
#include <stdint.h>

#define Bsz 2
#define Lsz 1024
#define Hsz 2048
#define Msz (Bsz*Lsz)          // 2048 rows
#define NST 16
#define CHUNK 128
#define NCHUNK (Lsz/CHUNK)     // 8
#define DBC_SPLITS 8

// tc gemm tile
#define TM 128
#define TN 256
#define KC 32
#define DST 3                               // pipeline stages
#define SB_OFF (128*36)                     // unsigned units
#define STG_U (SB_OFF + 256*36)             // 13824 unsigned / stage
#define SMEM_TOT (DST*STG_U*4)              // 165888 bytes

// ---------------- scratch ----------------
__device__ float d_h[(size_t)Msz*Hsz];        // rmsnorm out (tf32-rounded)
__device__ float d_xcpre[(size_t)Msz*Hsz];    // in_proj xc half (tf32-rounded)
__device__ float d_z[(size_t)Msz*Hsz];        // in_proj z half (fp32)
__device__ float d_xc[(size_t)Msz*Hsz];       // conv+silu out (fp32)
__device__ float d_dbc[(size_t)Msz*96];
__device__ float d_dbcp[(size_t)DBC_SPLITS*Msz*96];
__device__ float d_delta[(size_t)Msz*Hsz];
__device__ float d_g[(size_t)Msz*Hsz];        // y*silu(z) (tf32-rounded)
__device__ float d_Aexp[Hsz*NST];
__device__ float d_P[(size_t)Bsz*NCHUNK*Hsz*NST];
__device__ float d_S[(size_t)Bsz*NCHUNK*Hsz*NST];
__device__ float d_I[(size_t)Bsz*NCHUNK*Hsz*NST];
__device__ float d_ipw[(size_t)2*Hsz*Hsz];    // in_proj_w rounded
__device__ float d_opw[(size_t)Hsz*Hsz];      // out_proj_w rounded
__device__ float d_cwT[(size_t)Hsz*4*Hsz];    // conv_w transposed [n][k] rounded

// ---------------- helpers ----------------
__device__ __forceinline__ unsigned f2tf(float x){
    unsigned y; asm("cvt.rna.tf32.f32 %0, %1;" : "=r"(y) : "f"(x)); return y;
}
__device__ __forceinline__ float rtf(float x){ return __uint_as_float(f2tf(x)); }
__device__ __forceinline__ void mma8(float* c, const unsigned* a, const unsigned* b){
    asm volatile("mma.sync.aligned.m16n8k8.row.col.f32.tf32.tf32.f32 "
      "{%0,%1,%2,%3}, {%4,%5,%6,%7}, {%8,%9}, {%0,%1,%2,%3};"
      : "+f"(c[0]), "+f"(c[1]), "+f"(c[2]), "+f"(c[3])
      : "r"(a[0]), "r"(a[1]), "r"(a[2]), "r"(a[3]), "r"(b[0]), "r"(b[1]));
}
__device__ __forceinline__ void ldsm4(unsigned* r, uint32_t a){
    asm volatile("ldmatrix.sync.aligned.m8n8.x4.shared.b16 {%0,%1,%2,%3}, [%4];"
        : "=r"(r[0]), "=r"(r[1]), "=r"(r[2]), "=r"(r[3]) : "r"(a));
}
__device__ __forceinline__ uint32_t smem_u32(const void* p){
    uint32_t a; asm("{ .reg .u64 t; cvta.to.shared.u64 t, %1; cvt.u32.u64 %0, t; }" : "=r"(a) : "l"(p));
    return a;
}
__device__ __forceinline__ void cpa16(uint32_t dst, const float* src, int srcsize){
    asm volatile("cp.async.cg.shared.global [%0], [%1], 16, %2;"
        :: "r"(dst), "l"(src), "r"(srcsize) : "memory");
}
__device__ __forceinline__ void cp_commit(){ asm volatile("cp.async.commit_group;" ::: "memory"); }
__device__ __forceinline__ void cp_wait2(){ asm volatile("cp.async.wait_group 2;" ::: "memory"); }

// ---------------- prep kernels ----------------
__global__ void wround(const float* __restrict__ in, float* __restrict__ outp, int n4){
    int i = blockIdx.x*256 + threadIdx.x;
    if (i >= n4) return;
    float4 v = *(const float4*)(in + (size_t)i*4);
    v.x = rtf(v.x); v.y = rtf(v.y); v.z = rtf(v.z); v.w = rtf(v.w);
    *(float4*)(outp + (size_t)i*4) = v;
}

// conv_w [k=8192][n=2048] -> [n][k], tf32-rounded
__global__ void convT(const float* __restrict__ cw){
    __shared__ float tl[32][33];
    const int k0 = blockIdx.x*32, n0 = blockIdx.y*32;
    const int tx = threadIdx.x, ty = threadIdx.y;
    #pragma unroll
    for (int d = 0; d < 4; d++)
        tl[ty + d*8][tx] = cw[(size_t)(k0+ty+d*8)*Hsz + n0 + tx];
    __syncthreads();
    #pragma unroll
    for (int d = 0; d < 4; d++)
        d_cwT[(size_t)(n0+ty+d*8)*(4*Hsz) + k0 + tx] = rtf(tl[tx][ty+d*8]);
}

// ---------------- small kernels ----------------
__global__ void aexp_kernel(const float* __restrict__ alog) {
    int i = blockIdx.x*256 + threadIdx.x;
    if (i < Hsz*NST) d_Aexp[i] = -expf(alog[i]);
}

__global__ void rmsnorm_kernel(const float* __restrict__ x, const float* __restrict__ w) {
    const int m = blockIdx.x;
    const float* xr = x + (size_t)m*Hsz;
    float ss = 0.f;
    for (int i = threadIdx.x*4; i < Hsz; i += 1024) {
        float4 v = *(const float4*)(xr + i);
        ss += v.x*v.x + v.y*v.y + v.z*v.z + v.w*v.w;
    }
    __shared__ float red[8];
    #pragma unroll
    for (int o = 16; o; o >>= 1) ss += __shfl_xor_sync(0xffffffffu, ss, o);
    if ((threadIdx.x & 31) == 0) red[threadIdx.x >> 5] = ss;
    __syncthreads();
    if (threadIdx.x == 0) {
        float v = 0.f;
        #pragma unroll
        for (int j = 0; j < 8; j++) v += red[j];
        red[0] = rsqrtf(v * (1.0f/Hsz) + 1e-5f);
    }
    __syncthreads();
    const float sc = red[0];
    float* hr = d_h + (size_t)m*Hsz;
    for (int i = threadIdx.x*4; i < Hsz; i += 1024) {
        float4 v = *(const float4*)(xr + i);
        float4 wv = *(const float4*)(w + i);
        v.x = rtf(v.x*sc*wv.x); v.y = rtf(v.y*sc*wv.y);
        v.z = rtf(v.z*sc*wv.z); v.w = rtf(v.w*sc*wv.w);
        *(float4*)(hr + i) = v;
    }
}

// ====== tf32 tensor GEMM, cp.async 3-stage pipeline, ldmatrix fragments ======
// C = A(M,K) * W(N,K)^T. block 128x256, 512 thr, warp tile 32x64.
// EPI 0: in_proj split (n<H -> C rounded tf32, else -> C2 fp32)
// EPI 1: conv bias+silu -> C
// EPI 2: resid add -> C
template<int EPI, bool CONVA>
__global__ void __launch_bounds__(512, 1)
gemm_tc(const float* __restrict__ A, const float* __restrict__ W,
        float* __restrict__ C, float* __restrict__ C2,
        const float* __restrict__ aux, int K, int lda, int ldc)
{
    extern __shared__ __align__(16) unsigned sm[];
    const uint32_t smb = smem_u32(sm);
    const int t = threadIdx.x;
    const int lane = t & 31, w = t >> 5;
    const int gid = lane >> 2, tig = lane & 3;
    const int wm = (w & 3) * 32, wn = (w >> 2) * 64;
    const int n0 = blockIdx.x * TN, m0 = blockIdx.y * TM;
    const int r0 = t >> 3;                 // 0..63
    const int kc = (t & 7) * 4;
    const int nc = K / KC;

    // cp.async destination addresses (stage 0)
    const uint32_t dstA0 = smb + (uint32_t)((r0      )*36 + kc)*4;
    const uint32_t dstA1 = smb + (uint32_t)((r0 + 64 )*36 + kc)*4;
    uint32_t dstB[4];
    #pragma unroll
    for (int p = 0; p < 4; p++)
        dstB[p] = smb + (uint32_t)(SB_OFF + (r0 + 64*p)*36 + kc)*4;

    auto issue = [&](int c){
        if (c < nc) {
            const uint32_t so = (uint32_t)(c % DST) * (STG_U*4);
            const int kb = c * KC;
            if (!CONVA) {
                cpa16(dstA0 + so, A + (size_t)(m0 + r0)*lda + kb + kc, 16);
                cpa16(dstA1 + so, A + (size_t)(m0 + r0 + 64)*lda + kb + kc, 16);
            } else {
                const int tap = kb >> 11, kin = kb & (Hsz-1);
                #pragma unroll
                for (int i = 0; i < 2; i++) {
                    const int m = m0 + r0 + 64*i;
                    int ls = (m & 1023) + tap - 3;
                    const int sz = (ls >= 0) ? 16 : 0;
                    if (ls < 0) ls = 0;
                    cpa16((i ? dstA1 : dstA0) + so,
                          A + (size_t)((m & ~1023) + ls)*lda + kin + kc, sz);
                }
            }
            #pragma unroll
            for (int p = 0; p < 4; p++)
                cpa16(dstB[p] + so, W + (size_t)(n0 + r0 + 64*p)*K + kb + kc, 16);
        }
        cp_commit();
    };

    // ldmatrix source addresses (stage 0)
    const int lrow = lane & 15;
    const int lcol = (lane & 16) ? 4 : 0;
    uint32_t a_ad[2], b_ad[4];
    #pragma unroll
    for (int mi = 0; mi < 2; mi++)
        a_ad[mi] = smb + (uint32_t)(((wm + mi*16 + lrow)*36 + lcol)*4);
    #pragma unroll
    for (int p = 0; p < 4; p++)
        b_ad[p] = smb + (uint32_t)((SB_OFF + (wn + p*16 + lrow)*36 + lcol)*4);

    float acc[2][8][4];
    #pragma unroll
    for (int mi = 0; mi < 2; mi++)
        #pragma unroll
        for (int ni = 0; ni < 8; ni++)
            #pragma unroll
            for (int q = 0; q < 4; q++) acc[mi][ni][q] = 0.f;

    issue(0); issue(1);
    for (int c = 0; c < nc; c++) {
        issue(c + DST - 1);
        cp_wait2();
        __syncthreads();
        const uint32_t so = (uint32_t)(c % DST) * (STG_U*4);
        #pragma unroll
        for (int kk = 0; kk < 4; kk++) {
            unsigned af[2][4], bf[4][4];
            ldsm4(af[0], a_ad[0] + so + kk*32);
            ldsm4(af[1], a_ad[1] + so + kk*32);
            #pragma unroll
            for (int p = 0; p < 4; p++) ldsm4(bf[p], b_ad[p] + so + kk*32);
            #pragma unroll
            for (int mi = 0; mi < 2; mi++)
                #pragma unroll
                for (int ni = 0; ni < 8; ni++) {
                    unsigned bb[2] = { bf[ni>>1][ni&1], bf[ni>>1][2 + (ni&1)] };
                    mma8(acc[mi][ni], af[mi], bb);
                }
        }
        __syncthreads();
    }

    // epilogue
    #pragma unroll
    for (int mi = 0; mi < 2; mi++) {
        #pragma unroll
        for (int rr = 0; rr < 2; rr++) {
            const int m = m0 + wm + mi*16 + rr*8 + gid;
            #pragma unroll
            for (int ni = 0; ni < 8; ni++) {
                const int n = n0 + wn + ni*8 + tig*2;
                float v0 = acc[mi][ni][rr*2+0];
                float v1 = acc[mi][ni][rr*2+1];
                if (EPI == 0) {
                    if (n < Hsz)
                        *(float2*)&C[(size_t)m*ldc + n] = make_float2(rtf(v0), rtf(v1));
                    else
                        *(float2*)&C2[(size_t)m*ldc + n - Hsz] = make_float2(v0, v1);
                } else if (EPI == 1) {
                    v0 += aux[n];   v1 += aux[n+1];
                    v0 = v0 / (1.f + __expf(-v0));
                    v1 = v1 / (1.f + __expf(-v1));
                    *(float2*)&C[(size_t)m*ldc + n] = make_float2(v0, v1);
                } else {
                    v0 += aux[(size_t)m*ldc + n];
                    v1 += aux[(size_t)m*ldc + n + 1];
                    *(float2*)&C[(size_t)m*ldc + n] = make_float2(v0, v1);
                }
            }
        }
    }
}

// ---------------- fp32 SIMT GEMM (exact; small ops) ----------------
template<int EPI>
__global__ void __launch_bounds__(256)
gemm_wt(const float* __restrict__ A, const float* __restrict__ W,
        float* __restrict__ C, int M, int N, int K,
        int lda, int ldb, int ldc,
        const float* __restrict__ bias)
{
    __shared__ float As[8][128];
    __shared__ float Bs[8][128];
    const int t  = threadIdx.x;
    const int n0 = blockIdx.x * 128;
    const int m0 = blockIdx.y * 128;
    const int kslice = K / gridDim.z;
    const int kbeg = blockIdx.z * kslice;
    const int KT = kslice >> 3;

    const int ar = t >> 1;
    const int ak = (t & 1) * 4;
    const float* Ap = A + (size_t)(m0 + ar)*lda + kbeg + ak;
    const bool wok = (n0 + ar) < N;
    const float* Wp = W + (size_t)(n0 + ar)*ldb + kbeg + ak;

    float* Cb = C;
    if (EPI == 4) Cb = C + (size_t)blockIdx.z * M * ldc;

    const int tx = t & 15, ty = t >> 4;
    float acc[8][8];
    #pragma unroll
    for (int i = 0; i < 8; i++)
        #pragma unroll
        for (int j = 0; j < 8; j++) acc[i][j] = 0.f;

    float4 pa = *(const float4*)Ap;
    float4 pb = wok ? *(const float4*)Wp : make_float4(0.f,0.f,0.f,0.f);

    for (int kt = 0; kt < KT; ++kt) {
        As[ak+0][ar]=pa.x; As[ak+1][ar]=pa.y; As[ak+2][ar]=pa.z; As[ak+3][ar]=pa.w;
        Bs[ak+0][ar]=pb.x; Bs[ak+1][ar]=pb.y; Bs[ak+2][ar]=pb.z; Bs[ak+3][ar]=pb.w;
        __syncthreads();
        if (kt + 1 < KT) {
            pa = *(const float4*)(Ap + (size_t)(kt+1)*8);
            pb = wok ? *(const float4*)(Wp + (size_t)(kt+1)*8) : make_float4(0.f,0.f,0.f,0.f);
        }
        #pragma unroll
        for (int kk = 0; kk < 8; kk++) {
            float a[8], b[8];
            *(float4*)&a[0] = *(const float4*)&As[kk][ty*8];
            *(float4*)&a[4] = *(const float4*)&As[kk][ty*8+4];
            *(float4*)&b[0] = *(const float4*)&Bs[kk][tx*8];
            *(float4*)&b[4] = *(const float4*)&Bs[kk][tx*8+4];
            #pragma unroll
            for (int i = 0; i < 8; i++)
                #pragma unroll
                for (int j = 0; j < 8; j++)
                    acc[i][j] = fmaf(a[i], b[j], acc[i][j]);
        }
        __syncthreads();
    }

    #pragma unroll
    for (int i = 0; i < 8; i++) {
        const int m = m0 + ty*8 + i;
        #pragma unroll
        for (int j = 0; j < 8; j++) {
            const int n = n0 + tx*8 + j;
            if (n < N) {
                float v = acc[i][j];
                if (EPI == 2) { v += bias[n]; v = (v > 20.f) ? v : log1pf(__expf(v)); }
                Cb[(size_t)m*ldc + n] = v;
            }
        }
    }
}

__global__ void reduce_dbc() {
    int i = blockIdx.x*256 + threadIdx.x;
    if (i < Msz*96) {
        float s = 0.f;
        #pragma unroll
        for (int z = 0; z < DBC_SPLITS; z++) s += d_dbcp[(size_t)z*Msz*96 + i];
        d_dbc[i] = s;
    }
}

// ---------------- chunked selective scan ----------------
__global__ void __launch_bounds__(128) scan_pass1() {
    __shared__ float sB[CHUNK][NST];
    const int bid = blockIdx.x;
    const int ht = bid & 15;
    const int c  = (bid >> 4) & 7;
    const int b  = bid >> 7;
    const int h  = ht*128 + threadIdx.x;
    const int mbase = b*Lsz + c*CHUNK;

    for (int j = threadIdx.x; j < CHUNK*NST; j += 128) {
        int l = j >> 4, n = j & 15;
        sB[l][n] = d_dbc[(size_t)(mbase+l)*96 + 64 + n];
    }
    __syncthreads();

    float a[NST], p[NST], s[NST];
    #pragma unroll
    for (int n = 0; n < NST; n++) { a[n] = d_Aexp[h*NST + n]; p[n] = 1.f; s[n] = 0.f; }

    float dl = d_delta[(size_t)mbase*Hsz + h];
    float xv = d_xc[(size_t)mbase*Hsz + h];
    for (int l = 0; l < CHUNK; l++) {
        float dln = 0.f, xvn = 0.f;
        if (l + 1 < CHUNK) {
            dln = d_delta[(size_t)(mbase+l+1)*Hsz + h];
            xvn = d_xc[(size_t)(mbase+l+1)*Hsz + h];
        }
        const float du = dl * xv;
        #pragma unroll
        for (int n = 0; n < NST; n++) {
            float r = __expf(dl * a[n]);
            p[n] *= r;
            s[n] = fmaf(r, s[n], du * sB[l][n]);
        }
        dl = dln; xv = xvn;
    }
    size_t base = ((size_t)(b*NCHUNK + c)*Hsz + h)*NST;
    #pragma unroll
    for (int n = 0; n < NST; n++) { d_P[base+n] = p[n]; d_S[base+n] = s[n]; }
}

__global__ void scan_pass2() {
    int idx = blockIdx.x*256 + threadIdx.x;
    if (idx >= Bsz*Hsz*NST) return;
    int b  = idx / (Hsz*NST);
    int hn = idx % (Hsz*NST);
    float st = 0.f;
    for (int c = 0; c < NCHUNK; c++) {
        size_t o = (size_t)(b*NCHUNK + c)*Hsz*NST + hn;
        d_I[o] = st;
        st = d_P[o]*st + d_S[o];
    }
}

__global__ void __launch_bounds__(128) scan_pass3(const float* __restrict__ Din) {
    __shared__ float sBC[CHUNK][2*NST];
    const int bid = blockIdx.x;
    const int ht = bid & 15;
    const int c  = (bid >> 4) & 7;
    const int b  = bid >> 7;
    const int h  = ht*128 + threadIdx.x;
    const int mbase = b*Lsz + c*CHUNK;

    for (int j = threadIdx.x; j < CHUNK*2*NST; j += 128) {
        int l = j >> 5, cc = j & 31;
        sBC[l][cc] = d_dbc[(size_t)(mbase+l)*96 + 64 + cc];
    }
    __syncthreads();

    float a[NST], s[NST];
    size_t base = ((size_t)(b*NCHUNK + c)*Hsz + h)*NST;
    #pragma unroll
    for (int n = 0; n < NST; n++) { a[n] = d_Aexp[h*NST + n]; s[n] = d_I[base+n]; }
    const float Dh = Din[h];

    float dl = d_delta[(size_t)mbase*Hsz + h];
    float xv = d_xc[(size_t)mbase*Hsz + h];
    for (int l = 0; l < CHUNK; l++) {
        float dln = 0.f, xvn = 0.f;
        if (l + 1 < CHUNK) {
            dln = d_delta[(size_t)(mbase+l+1)*Hsz + h];
            xvn = d_xc[(size_t)(mbase+l+1)*Hsz + h];
        }
        const float du = dl * xv;
        float y = 0.f;
        #pragma unroll
        for (int n = 0; n < NST; n++) {
            float r = __expf(dl * a[n]);
            s[n] = fmaf(r, s[n], du * sBC[l][n]);
            y = fmaf(s[n], sBC[l][NST+n], y);
        }
        y = fmaf(Dh, xv, y);
        const int m = mbase + l;
        float z = d_z[(size_t)m*Hsz + h];
        float sz = z / (1.f + __expf(-z));
        d_g[(size_t)m*Hsz + h] = rtf(y * sz);
        dl = dln; xv = xvn;
    }
}

// ---------------- launch ----------------
extern "C" void kernel_launch(void* const* d_in, const int* in_sizes, int n_in,
                              void* d_out, int out_size) {
    const float* x          = (const float*)d_in[0];
    const float* norm_w     = (const float*)d_in[1];
    const float* in_proj_w  = (const float*)d_in[2];
    const float* conv_w     = (const float*)d_in[3];
    const float* conv_b     = (const float*)d_in[4];
    const float* x_proj_w   = (const float*)d_in[5];
    const float* dt_proj_w  = (const float*)d_in[6];
    const float* dt_proj_b  = (const float*)d_in[7];
    const float* A_log      = (const float*)d_in[8];
    const float* Dv         = (const float*)d_in[9];
    const float* out_proj_w = (const float*)d_in[10];
    float* out = (float*)d_out;

    static int attr_done = 0;
    if (!attr_done) {
        cudaFuncSetAttribute(gemm_tc<0,false>, cudaFuncAttributeMaxDynamicSharedMemorySize, SMEM_TOT);
        cudaFuncSetAttribute(gemm_tc<1,true >, cudaFuncAttributeMaxDynamicSharedMemorySize, SMEM_TOT);
        cudaFuncSetAttribute(gemm_tc<2,false>, cudaFuncAttributeMaxDynamicSharedMemorySize, SMEM_TOT);
        attr_done = 1;
    }

    float *p_h, *p_xcpre, *p_z, *p_xc, *p_dbc, *p_dbcp, *p_delta, *p_g;
    float *p_ipw, *p_opw, *p_cwT;
    cudaGetSymbolAddress((void**)&p_h, d_h);
    cudaGetSymbolAddress((void**)&p_xcpre, d_xcpre);
    cudaGetSymbolAddress((void**)&p_z, d_z);
    cudaGetSymbolAddress((void**)&p_xc, d_xc);
    cudaGetSymbolAddress((void**)&p_dbc, d_dbc);
    cudaGetSymbolAddress((void**)&p_dbcp, d_dbcp);
    cudaGetSymbolAddress((void**)&p_delta, d_delta);
    cudaGetSymbolAddress((void**)&p_g, d_g);
    cudaGetSymbolAddress((void**)&p_ipw, d_ipw);
    cudaGetSymbolAddress((void**)&p_opw, d_opw);
    cudaGetSymbolAddress((void**)&p_cwT, d_cwT);

    // 0. prep: round weights to tf32 (once per graph replay; cheap)
    wround<<<(2*Hsz*Hsz/4 + 255)/256, 256>>>(in_proj_w, p_ipw, 2*Hsz*Hsz/4);
    wround<<<(Hsz*Hsz/4 + 255)/256, 256>>>(out_proj_w, p_opw, Hsz*Hsz/4);
    convT<<<dim3(4*Hsz/32, Hsz/32), dim3(32,8)>>>(conv_w);
    aexp_kernel<<<(Hsz*NST + 255)/256, 256>>>(A_log);
    // 1. rmsnorm (emits tf32-rounded h)
    rmsnorm_kernel<<<Msz, 256>>>(x, norm_w);
    // 2. in_proj: xz = h @ W^T (M=2048, N=4096, K=2048) -> xcpre (rounded) | z (fp32)
    gemm_tc<0,false><<<dim3(2*Hsz/TN, Msz/TM), 512, SMEM_TOT>>>(
        p_h, p_ipw, p_xcpre, p_z, nullptr, Hsz, Hsz, Hsz);
    // 3. conv: xc = silu(conv(xcpre) + b)  (K=8192 virtual over 4 taps)
    gemm_tc<1,true><<<dim3(Hsz/TN, Msz/TM), 512, SMEM_TOT>>>(
        p_xcpre, p_cwT, p_xc, nullptr, conv_b, 4*Hsz, Hsz, Hsz);
    // 4. dBC = xc @ x_proj_w.T  (exact fp32, split-K)
    gemm_wt<4><<<dim3(1,16,DBC_SPLITS), 256>>>(p_xc, x_proj_w, p_dbcp,
                                               Msz, 96, Hsz, Hsz, Hsz, 96, nullptr);
    reduce_dbc<<<(Msz*96 + 255)/256, 256>>>();
    // 5. delta = softplus(dBC[:, :64] @ dt_proj_w.T + b)  (exact fp32)
    gemm_wt<2><<<dim3(16,16,1), 256>>>(p_dbc, dt_proj_w, p_delta,
                                       Msz, Hsz, 64, 96, 64, Hsz, dt_proj_b);
    // 6. chunked selective scan -> g = y * silu(z) (rounded)
    scan_pass1<<<Bsz*NCHUNK*(Hsz/128), 128>>>();
    scan_pass2<<<(Bsz*Hsz*NST + 255)/256, 256>>>();
    scan_pass3<<<Bsz*NCHUNK*(Hsz/128), 128>>>(Dv);
    // 7. out = x + g @ out_proj_w.T
    gemm_tc<2,false><<<dim3(Hsz/TN, Msz/TM), 512, SMEM_TOT>>>(
        p_g, p_opw, out, nullptr, x, Hsz, Hsz, Hsz);
}

// round 6
// speedup vs baseline: 4.9541x; 1.7094x over previous
#include <cuda_runtime.h>
#include <cuda_fp16.h>
#include <math.h>
#include <stdint.h>

#define Bsz 2
#define Lsz 1024
#define Hsz 2048
#define Msz (Bsz*Lsz)          // 2048 rows
#define NST 16
#define CHUNK 128
#define NCHUNK (Lsz/CHUNK)     // 8
#define DBC_SPLITS 8

// tc gemm tile (fp16 path)
#define TM 128
#define TN 256
#define KC 64
#define DST 3
#define RS 72                               // padded row stride in halves
#define OFFB_H (128*RS)                     // B offset in halves
#define STG_H ((128+256)*RS)                // halves per stage (27648)
#define SMEM_TOT (DST*STG_H*2)              // 165888 bytes

// ---------------- scratch ----------------
__device__ __half d_h16[(size_t)Msz*Hsz];       // rmsnorm out (fp16)
__device__ __half d_xcp16[(size_t)Msz*Hsz];     // in_proj xc half (fp16)
__device__ float  d_z[(size_t)Msz*Hsz];         // in_proj z half (fp32)
__device__ float  d_xc[(size_t)Msz*Hsz];        // conv+silu out (fp32)
__device__ float  d_dbc[(size_t)Msz*96];
__device__ float  d_dbcp[(size_t)DBC_SPLITS*Msz*96];
__device__ float  d_delta[(size_t)Msz*Hsz];
__device__ __half d_g16[(size_t)Msz*Hsz];       // y*silu(z) (fp16)
__device__ float  d_Aexp[Hsz*NST];
__device__ float  d_P[(size_t)Bsz*NCHUNK*Hsz*NST];
__device__ float  d_S[(size_t)Bsz*NCHUNK*Hsz*NST];
__device__ float  d_I[(size_t)Bsz*NCHUNK*Hsz*NST];
__device__ __half d_ipw16[(size_t)2*Hsz*Hsz];   // in_proj_w fp16
__device__ __half d_opw16[(size_t)Hsz*Hsz];     // out_proj_w fp16
__device__ __half d_cwT16[(size_t)Hsz*4*Hsz];   // conv_w transposed [n][k=8192] fp16

// ---------------- helpers ----------------
__device__ __forceinline__ void mma16(float* c, const unsigned* a, const unsigned* b){
    asm volatile("mma.sync.aligned.m16n8k16.row.col.f32.f16.f16.f32 "
      "{%0,%1,%2,%3}, {%4,%5,%6,%7}, {%8,%9}, {%0,%1,%2,%3};"
      : "+f"(c[0]), "+f"(c[1]), "+f"(c[2]), "+f"(c[3])
      : "r"(a[0]), "r"(a[1]), "r"(a[2]), "r"(a[3]), "r"(b[0]), "r"(b[1]));
}
__device__ __forceinline__ void ldsm4(unsigned* r, uint32_t a){
    asm volatile("ldmatrix.sync.aligned.m8n8.x4.shared.b16 {%0,%1,%2,%3}, [%4];"
        : "=r"(r[0]), "=r"(r[1]), "=r"(r[2]), "=r"(r[3]) : "r"(a));
}
__device__ __forceinline__ uint32_t smem_u32(const void* p){
    uint32_t a; asm("{ .reg .u64 t; cvta.to.shared.u64 t, %1; cvt.u32.u64 %0, t; }" : "=r"(a) : "l"(p));
    return a;
}
__device__ __forceinline__ void cpa16(uint32_t dst, const __half* src, int srcsize){
    asm volatile("cp.async.cg.shared.global [%0], [%1], 16, %2;"
        :: "r"(dst), "l"(src), "r"(srcsize) : "memory");
}
__device__ __forceinline__ void cp_commit(){ asm volatile("cp.async.commit_group;" ::: "memory"); }
__device__ __forceinline__ void cp_wait2(){ asm volatile("cp.async.wait_group 2;" ::: "memory"); }

// ---------------- prep kernels ----------------
__global__ void whalf(const float* __restrict__ in, __half* __restrict__ outp, int n4){
    int i = blockIdx.x*256 + threadIdx.x;
    if (i >= n4) return;
    float4 v = *(const float4*)(in + (size_t)i*4);
    __half2 h01 = __floats2half2_rn(v.x, v.y);
    __half2 h23 = __floats2half2_rn(v.z, v.w);
    *(uint2*)(outp + (size_t)i*4) = make_uint2(*(unsigned*)&h01, *(unsigned*)&h23);
}

// conv_w [k=8192][n=2048] -> [n][k] fp16
__global__ void convT(const float* __restrict__ cw){
    __shared__ float tl[32][33];
    const int k0 = blockIdx.x*32, n0 = blockIdx.y*32;
    const int tx = threadIdx.x, ty = threadIdx.y;
    #pragma unroll
    for (int d = 0; d < 4; d++)
        tl[ty + d*8][tx] = cw[(size_t)(k0+ty+d*8)*Hsz + n0 + tx];
    __syncthreads();
    #pragma unroll
    for (int d = 0; d < 4; d++)
        d_cwT16[(size_t)(n0+ty+d*8)*(4*Hsz) + k0 + tx] = __float2half_rn(tl[tx][ty+d*8]);
}

// ---------------- small kernels ----------------
__global__ void aexp_kernel(const float* __restrict__ alog) {
    int i = blockIdx.x*256 + threadIdx.x;
    if (i < Hsz*NST) d_Aexp[i] = -expf(alog[i]);
}

__global__ void rmsnorm_kernel(const float* __restrict__ x, const float* __restrict__ w) {
    const int m = blockIdx.x;
    const float* xr = x + (size_t)m*Hsz;
    float ss = 0.f;
    for (int i = threadIdx.x*4; i < Hsz; i += 1024) {
        float4 v = *(const float4*)(xr + i);
        ss += v.x*v.x + v.y*v.y + v.z*v.z + v.w*v.w;
    }
    __shared__ float red[8];
    #pragma unroll
    for (int o = 16; o; o >>= 1) ss += __shfl_xor_sync(0xffffffffu, ss, o);
    if ((threadIdx.x & 31) == 0) red[threadIdx.x >> 5] = ss;
    __syncthreads();
    if (threadIdx.x == 0) {
        float v = 0.f;
        #pragma unroll
        for (int j = 0; j < 8; j++) v += red[j];
        red[0] = rsqrtf(v * (1.0f/Hsz) + 1e-5f);
    }
    __syncthreads();
    const float sc = red[0];
    for (int i = threadIdx.x*4; i < Hsz; i += 1024) {
        float4 v = *(const float4*)(xr + i);
        float4 wv = *(const float4*)(w + i);
        __half2 h01 = __floats2half2_rn(v.x*sc*wv.x, v.y*sc*wv.y);
        __half2 h23 = __floats2half2_rn(v.z*sc*wv.z, v.w*sc*wv.w);
        *(uint2*)(d_h16 + (size_t)m*Hsz + i) = make_uint2(*(unsigned*)&h01, *(unsigned*)&h23);
    }
}

// ====== fp16 tensor GEMM, cp.async 3-stage pipeline, m16n8k16 ======
// C = A(M,K) * W(N,K)^T. block 128x256, 512 thr, warp tile 32x64.
// EPI 0: in_proj split (n<H -> fp16 xcp, else -> fp32 z)
// EPI 1: conv bias+silu -> fp32 C
// EPI 2: resid add -> fp32 C
template<int EPI, bool CONVA>
__global__ void __launch_bounds__(512, 1)
gemm_tc(const __half* __restrict__ A, const __half* __restrict__ W,
        float* __restrict__ C, float* __restrict__ C2,
        const float* __restrict__ aux, int K, int lda, int ldc)
{
    extern __shared__ __align__(16) __half sm[];
    const uint32_t smb = smem_u32(sm);
    const int t = threadIdx.x;
    const int lane = t & 31, w = t >> 5;
    const int gid = lane >> 2, tig = lane & 3;
    const int wm = (w & 3) * 32, wn = (w >> 2) * 64;
    const int n0 = blockIdx.x * TN, m0 = blockIdx.y * TM;
    const int nc = K / KC;

    // cp.async destinations (stage 0), 16B per op = 8 halves
    uint32_t dstA[2], dstB[4];
    int rowA[2], kcA[2], rowB[4], kcB[4];
    #pragma unroll
    for (int i = 0; i < 2; i++) {
        int slot = t + 512*i;
        rowA[i] = slot >> 3; kcA[i] = (slot & 7) * 8;
        dstA[i] = smb + (uint32_t)(rowA[i]*RS + kcA[i])*2;
    }
    #pragma unroll
    for (int i = 0; i < 4; i++) {
        int slot = t + 512*i;
        rowB[i] = slot >> 3; kcB[i] = (slot & 7) * 8;
        dstB[i] = smb + (uint32_t)(OFFB_H + rowB[i]*RS + kcB[i])*2;
    }

    auto issue = [&](int c){
        if (c < nc) {
            const uint32_t so = (uint32_t)(c % DST) * (STG_H*2);
            const int kb = c * KC;
            if (!CONVA) {
                #pragma unroll
                for (int i = 0; i < 2; i++)
                    cpa16(dstA[i] + so, A + (size_t)(m0 + rowA[i])*lda + kb + kcA[i], 16);
            } else {
                const int tap = kb >> 11, kin = kb & (Hsz-1);
                #pragma unroll
                for (int i = 0; i < 2; i++) {
                    const int m = m0 + rowA[i];
                    int ls = (m & 1023) + tap - 3;
                    const int sz = (ls >= 0) ? 16 : 0;
                    if (ls < 0) ls = 0;
                    cpa16(dstA[i] + so, A + (size_t)((m & ~1023) + ls)*lda + kin + kcA[i], sz);
                }
            }
            #pragma unroll
            for (int i = 0; i < 4; i++)
                cpa16(dstB[i] + so, W + (size_t)(n0 + rowB[i])*K + kb + kcB[i], 16);
        }
        cp_commit();
    };

    // ldmatrix source addresses (stage 0)
    uint32_t a_ad[2], b_ad[4];
    {
        const int arow = (lane & 15), acol = (lane >> 4) * 8;
        #pragma unroll
        for (int mi = 0; mi < 2; mi++)
            a_ad[mi] = smb + (uint32_t)(((wm + mi*16 + arow)*RS + acol))*2;
        const int brow = ((lane & 16) >> 1) + (lane & 7);
        const int bcol = (lane & 8);
        #pragma unroll
        for (int nq = 0; nq < 4; nq++)
            b_ad[nq] = smb + (uint32_t)((OFFB_H + (wn + nq*16 + brow)*RS + bcol))*2;
    }

    float acc[2][8][4];
    #pragma unroll
    for (int mi = 0; mi < 2; mi++)
        #pragma unroll
        for (int ni = 0; ni < 8; ni++)
            #pragma unroll
            for (int q = 0; q < 4; q++) acc[mi][ni][q] = 0.f;

    issue(0); issue(1);
    for (int c = 0; c < nc; c++) {
        issue(c + DST - 1);
        cp_wait2();
        __syncthreads();
        const uint32_t so = (uint32_t)(c % DST) * (STG_H*2);
        #pragma unroll
        for (int ks = 0; ks < 4; ks++) {         // 4 x k16
            unsigned af[2][4], bf[4][4];
            ldsm4(af[0], a_ad[0] + so + ks*32);
            ldsm4(af[1], a_ad[1] + so + ks*32);
            #pragma unroll
            for (int nq = 0; nq < 4; nq++) ldsm4(bf[nq], b_ad[nq] + so + ks*32);
            #pragma unroll
            for (int mi = 0; mi < 2; mi++)
                #pragma unroll
                for (int ni = 0; ni < 8; ni++)
                    mma16(acc[mi][ni], af[mi], &bf[ni>>1][(ni&1)*2]);
        }
        __syncthreads();
    }

    // epilogue (c-fragment mapping identical to tf32 path)
    #pragma unroll
    for (int mi = 0; mi < 2; mi++) {
        #pragma unroll
        for (int rr = 0; rr < 2; rr++) {
            const int m = m0 + wm + mi*16 + rr*8 + gid;
            #pragma unroll
            for (int ni = 0; ni < 8; ni++) {
                const int n = n0 + wn + ni*8 + tig*2;
                float v0 = acc[mi][ni][rr*2+0];
                float v1 = acc[mi][ni][rr*2+1];
                if (EPI == 0) {
                    if (n < Hsz) {
                        __half2 hp = __floats2half2_rn(v0, v1);
                        *(unsigned*)&d_xcp16[(size_t)m*Hsz + n] = *(unsigned*)&hp;
                    } else {
                        *(float2*)&C2[(size_t)m*ldc + n - Hsz] = make_float2(v0, v1);
                    }
                } else if (EPI == 1) {
                    v0 += aux[n];   v1 += aux[n+1];
                    v0 = v0 / (1.f + __expf(-v0));
                    v1 = v1 / (1.f + __expf(-v1));
                    *(float2*)&C[(size_t)m*ldc + n] = make_float2(v0, v1);
                } else {
                    v0 += aux[(size_t)m*ldc + n];
                    v1 += aux[(size_t)m*ldc + n + 1];
                    *(float2*)&C[(size_t)m*ldc + n] = make_float2(v0, v1);
                }
            }
        }
    }
}

// ---------------- fp32 SIMT GEMM (exact; small ops) ----------------
template<int EPI>
__global__ void __launch_bounds__(256)
gemm_wt(const float* __restrict__ A, const float* __restrict__ W,
        float* __restrict__ C, int M, int N, int K,
        int lda, int ldb, int ldc,
        const float* __restrict__ bias)
{
    __shared__ float As[8][128];
    __shared__ float Bs[8][128];
    const int t  = threadIdx.x;
    const int n0 = blockIdx.x * 128;
    const int m0 = blockIdx.y * 128;
    const int kslice = K / gridDim.z;
    const int kbeg = blockIdx.z * kslice;
    const int KT = kslice >> 3;

    const int ar = t >> 1;
    const int ak = (t & 1) * 4;
    const float* Ap = A + (size_t)(m0 + ar)*lda + kbeg + ak;
    const bool wok = (n0 + ar) < N;
    const float* Wp = W + (size_t)(n0 + ar)*ldb + kbeg + ak;

    float* Cb = C;
    if (EPI == 4) Cb = C + (size_t)blockIdx.z * M * ldc;

    const int tx = t & 15, ty = t >> 4;
    float acc[8][8];
    #pragma unroll
    for (int i = 0; i < 8; i++)
        #pragma unroll
        for (int j = 0; j < 8; j++) acc[i][j] = 0.f;

    float4 pa = *(const float4*)Ap;
    float4 pb = wok ? *(const float4*)Wp : make_float4(0.f,0.f,0.f,0.f);

    for (int kt = 0; kt < KT; ++kt) {
        As[ak+0][ar]=pa.x; As[ak+1][ar]=pa.y; As[ak+2][ar]=pa.z; As[ak+3][ar]=pa.w;
        Bs[ak+0][ar]=pb.x; Bs[ak+1][ar]=pb.y; Bs[ak+2][ar]=pb.z; Bs[ak+3][ar]=pb.w;
        __syncthreads();
        if (kt + 1 < KT) {
            pa = *(const float4*)(Ap + (size_t)(kt+1)*8);
            pb = wok ? *(const float4*)(Wp + (size_t)(kt+1)*8) : make_float4(0.f,0.f,0.f,0.f);
        }
        #pragma unroll
        for (int kk = 0; kk < 8; kk++) {
            float a[8], b[8];
            *(float4*)&a[0] = *(const float4*)&As[kk][ty*8];
            *(float4*)&a[4] = *(const float4*)&As[kk][ty*8+4];
            *(float4*)&b[0] = *(const float4*)&Bs[kk][tx*8];
            *(float4*)&b[4] = *(const float4*)&Bs[kk][tx*8+4];
            #pragma unroll
            for (int i = 0; i < 8; i++)
                #pragma unroll
                for (int j = 0; j < 8; j++)
                    acc[i][j] = fmaf(a[i], b[j], acc[i][j]);
        }
        __syncthreads();
    }

    #pragma unroll
    for (int i = 0; i < 8; i++) {
        const int m = m0 + ty*8 + i;
        #pragma unroll
        for (int j = 0; j < 8; j++) {
            const int n = n0 + tx*8 + j;
            if (n < N) {
                float v = acc[i][j];
                if (EPI == 2) { v += bias[n]; v = (v > 20.f) ? v : log1pf(__expf(v)); }
                Cb[(size_t)m*ldc + n] = v;
            }
        }
    }
}

__global__ void reduce_dbc() {
    int i = blockIdx.x*256 + threadIdx.x;
    if (i < Msz*96) {
        float s = 0.f;
        #pragma unroll
        for (int z = 0; z < DBC_SPLITS; z++) s += d_dbcp[(size_t)z*Msz*96 + i];
        d_dbc[i] = s;
    }
}

// ---------------- chunked selective scan ----------------
__global__ void __launch_bounds__(128) scan_pass1() {
    __shared__ float sB[CHUNK][NST];
    const int bid = blockIdx.x;
    const int ht = bid & 15;
    const int c  = (bid >> 4) & 7;
    const int b  = bid >> 7;
    const int h  = ht*128 + threadIdx.x;
    const int mbase = b*Lsz + c*CHUNK;

    for (int j = threadIdx.x; j < CHUNK*NST; j += 128) {
        int l = j >> 4, n = j & 15;
        sB[l][n] = d_dbc[(size_t)(mbase+l)*96 + 64 + n];
    }
    __syncthreads();

    float a[NST], p[NST], s[NST];
    #pragma unroll
    for (int n = 0; n < NST; n++) { a[n] = d_Aexp[h*NST + n]; p[n] = 1.f; s[n] = 0.f; }

    float dl = d_delta[(size_t)mbase*Hsz + h];
    float xv = d_xc[(size_t)mbase*Hsz + h];
    for (int l = 0; l < CHUNK; l++) {
        float dln = 0.f, xvn = 0.f;
        if (l + 1 < CHUNK) {
            dln = d_delta[(size_t)(mbase+l+1)*Hsz + h];
            xvn = d_xc[(size_t)(mbase+l+1)*Hsz + h];
        }
        const float du = dl * xv;
        #pragma unroll
        for (int n = 0; n < NST; n++) {
            float r = __expf(dl * a[n]);
            p[n] *= r;
            s[n] = fmaf(r, s[n], du * sB[l][n]);
        }
        dl = dln; xv = xvn;
    }
    size_t base = ((size_t)(b*NCHUNK + c)*Hsz + h)*NST;
    #pragma unroll
    for (int n = 0; n < NST; n++) { d_P[base+n] = p[n]; d_S[base+n] = s[n]; }
}

__global__ void scan_pass2() {
    int idx = blockIdx.x*256 + threadIdx.x;
    if (idx >= Bsz*Hsz*NST) return;
    int b  = idx / (Hsz*NST);
    int hn = idx % (Hsz*NST);
    float st = 0.f;
    for (int c = 0; c < NCHUNK; c++) {
        size_t o = (size_t)(b*NCHUNK + c)*Hsz*NST + hn;
        d_I[o] = st;
        st = d_P[o]*st + d_S[o];
    }
}

__global__ void __launch_bounds__(128) scan_pass3(const float* __restrict__ Din) {
    __shared__ float sBC[CHUNK][2*NST];
    const int bid = blockIdx.x;
    const int ht = bid & 15;
    const int c  = (bid >> 4) & 7;
    const int b  = bid >> 7;
    const int h  = ht*128 + threadIdx.x;
    const int mbase = b*Lsz + c*CHUNK;

    for (int j = threadIdx.x; j < CHUNK*2*NST; j += 128) {
        int l = j >> 5, cc = j & 31;
        sBC[l][cc] = d_dbc[(size_t)(mbase+l)*96 + 64 + cc];
    }
    __syncthreads();

    float a[NST], s[NST];
    size_t base = ((size_t)(b*NCHUNK + c)*Hsz + h)*NST;
    #pragma unroll
    for (int n = 0; n < NST; n++) { a[n] = d_Aexp[h*NST + n]; s[n] = d_I[base+n]; }
    const float Dh = Din[h];

    float dl = d_delta[(size_t)mbase*Hsz + h];
    float xv = d_xc[(size_t)mbase*Hsz + h];
    for (int l = 0; l < CHUNK; l++) {
        float dln = 0.f, xvn = 0.f;
        if (l + 1 < CHUNK) {
            dln = d_delta[(size_t)(mbase+l+1)*Hsz + h];
            xvn = d_xc[(size_t)(mbase+l+1)*Hsz + h];
        }
        const float du = dl * xv;
        float y = 0.f;
        #pragma unroll
        for (int n = 0; n < NST; n++) {
            float r = __expf(dl * a[n]);
            s[n] = fmaf(r, s[n], du * sBC[l][n]);
            y = fmaf(s[n], sBC[l][NST+n], y);
        }
        y = fmaf(Dh, xv, y);
        const int m = mbase + l;
        float z = d_z[(size_t)m*Hsz + h];
        float sz = z / (1.f + __expf(-z));
        d_g16[(size_t)m*Hsz + h] = __float2half_rn(y * sz);
        dl = dln; xv = xvn;
    }
}

// ---------------- launch ----------------
extern "C" void kernel_launch(void* const* d_in, const int* in_sizes, int n_in,
                              void* d_out, int out_size) {
    const float* x          = (const float*)d_in[0];
    const float* norm_w     = (const float*)d_in[1];
    const float* in_proj_w  = (const float*)d_in[2];
    const float* conv_w     = (const float*)d_in[3];
    const float* conv_b     = (const float*)d_in[4];
    const float* x_proj_w   = (const float*)d_in[5];
    const float* dt_proj_w  = (const float*)d_in[6];
    const float* dt_proj_b  = (const float*)d_in[7];
    const float* A_log      = (const float*)d_in[8];
    const float* Dv         = (const float*)d_in[9];
    const float* out_proj_w = (const float*)d_in[10];
    float* out = (float*)d_out;

    static int attr_done = 0;
    if (!attr_done) {
        cudaFuncSetAttribute(gemm_tc<0,false>, cudaFuncAttributeMaxDynamicSharedMemorySize, SMEM_TOT);
        cudaFuncSetAttribute(gemm_tc<1,true >, cudaFuncAttributeMaxDynamicSharedMemorySize, SMEM_TOT);
        cudaFuncSetAttribute(gemm_tc<2,false>, cudaFuncAttributeMaxDynamicSharedMemorySize, SMEM_TOT);
        attr_done = 1;
    }

    __half *p_h16, *p_xcp16, *p_g16, *p_ipw16, *p_opw16, *p_cwT16;
    float *p_z, *p_xc, *p_dbc, *p_dbcp, *p_delta;
    cudaGetSymbolAddress((void**)&p_h16, d_h16);
    cudaGetSymbolAddress((void**)&p_xcp16, d_xcp16);
    cudaGetSymbolAddress((void**)&p_g16, d_g16);
    cudaGetSymbolAddress((void**)&p_ipw16, d_ipw16);
    cudaGetSymbolAddress((void**)&p_opw16, d_opw16);
    cudaGetSymbolAddress((void**)&p_cwT16, d_cwT16);
    cudaGetSymbolAddress((void**)&p_z, d_z);
    cudaGetSymbolAddress((void**)&p_xc, d_xc);
    cudaGetSymbolAddress((void**)&p_dbc, d_dbc);
    cudaGetSymbolAddress((void**)&p_dbcp, d_dbcp);
    cudaGetSymbolAddress((void**)&p_delta, d_delta);

    // 0. prep: fp16 weights (+ conv transpose)
    whalf<<<(2*Hsz*Hsz/4 + 255)/256, 256>>>(in_proj_w, p_ipw16, 2*Hsz*Hsz/4);
    whalf<<<(Hsz*Hsz/4 + 255)/256, 256>>>(out_proj_w, p_opw16, Hsz*Hsz/4);
    convT<<<dim3(4*Hsz/32, Hsz/32), dim3(32,8)>>>(conv_w);
    aexp_kernel<<<(Hsz*NST + 255)/256, 256>>>(A_log);
    // 1. rmsnorm (emits fp16 h)
    rmsnorm_kernel<<<Msz, 256>>>(x, norm_w);
    // 2. in_proj: xz = h @ W^T (M=2048, N=4096, K=2048) -> xcp16 | z(fp32)
    gemm_tc<0,false><<<dim3(2*Hsz/TN, Msz/TM), 512, SMEM_TOT>>>(
        p_h16, p_ipw16, nullptr, p_z, nullptr, Hsz, Hsz, Hsz);
    // 3. conv: xc = silu(conv(xcp) + b)  (K=8192 virtual over 4 taps)
    gemm_tc<1,true><<<dim3(Hsz/TN, Msz/TM), 512, SMEM_TOT>>>(
        p_xcp16, p_cwT16, p_xc, nullptr, conv_b, 4*Hsz, Hsz, Hsz);
    // 4. dBC = xc @ x_proj_w.T  (exact fp32, split-K)
    gemm_wt<4><<<dim3(1,16,DBC_SPLITS), 256>>>(p_xc, x_proj_w, p_dbcp,
                                               Msz, 96, Hsz, Hsz, Hsz, 96, nullptr);
    reduce_dbc<<<(Msz*96 + 255)/256, 256>>>();
    // 5. delta = softplus(dBC[:, :64] @ dt_proj_w.T + b)  (exact fp32)
    gemm_wt<2><<<dim3(16,16,1), 256>>>(p_dbc, dt_proj_w, p_delta,
                                       Msz, Hsz, 64, 96, 64, Hsz, dt_proj_b);
    // 6. chunked selective scan -> g (fp16)
    scan_pass1<<<Bsz*NCHUNK*(Hsz/128), 128>>>();
    scan_pass2<<<(Bsz*Hsz*NST + 255)/256, 256>>>();
    scan_pass3<<<Bsz*NCHUNK*(Hsz/128), 128>>>(Dv);
    // 7. out = x + g @ out_proj_w.T
    gemm_tc<2,false><<<dim3(Hsz/TN, Msz/TM), 512, SMEM_TOT>>>(
        p_g16, p_opw16, out, nullptr, x, Hsz, Hsz, Hsz);
}

// round 7
// speedup vs baseline: 5.3684x; 1.0836x over previous
#include <cuda_runtime.h>
#include <cuda_fp16.h>
#include <math.h>
#include <stdint.h>

#define Bsz 2
#define Lsz 1024
#define Hsz 2048
#define Msz (Bsz*Lsz)          // 2048 rows
#define NST 16
#define CHUNK 128
#define NCHUNK (Lsz/CHUNK)     // 8
#define DBC_SPLITS 8

// tc gemm tile (fp16 path)
#define TM 128
#define TN 256
#define KC 64
#define DST 4
#define RS 72                               // padded row stride in halves
#define OFFB_H (128*RS)                     // B offset in halves
#define STG_H ((128+256)*RS)                // halves per stage (27648)
#define SMEM_TOT (DST*STG_H*2)              // 221184 bytes

// ---------------- scratch ----------------
__device__ __half d_h16[(size_t)Msz*Hsz];       // rmsnorm out (fp16)
__device__ __half d_xcp16[(size_t)Msz*Hsz];     // in_proj xc half (fp16)
__device__ float  d_z[(size_t)Msz*Hsz];         // in_proj z half (fp32)
__device__ float  d_xc[(size_t)Msz*Hsz];        // conv+silu out (fp32)
__device__ float  d_dbc[(size_t)Msz*96];
__device__ float  d_dbcp[(size_t)DBC_SPLITS*Msz*96];
__device__ float  d_delta[(size_t)Msz*Hsz];
__device__ __half d_g16[(size_t)Msz*Hsz];       // y*silu(z) (fp16)
__device__ float  d_Aexp[Hsz*NST];
__device__ float  d_P[(size_t)Bsz*NCHUNK*Hsz*NST];
__device__ float  d_S[(size_t)Bsz*NCHUNK*Hsz*NST];
__device__ float  d_I[(size_t)Bsz*NCHUNK*Hsz*NST];
__device__ __half d_ipw16[(size_t)2*Hsz*Hsz];   // in_proj_w fp16
__device__ __half d_opw16[(size_t)Hsz*Hsz];     // out_proj_w fp16
__device__ __half d_cwT16[(size_t)Hsz*4*Hsz];   // conv_w transposed [n][k=8192] fp16

// ---------------- helpers ----------------
__device__ __forceinline__ void mma16(float* c, const unsigned* a, const unsigned* b){
    asm volatile("mma.sync.aligned.m16n8k16.row.col.f32.f16.f16.f32 "
      "{%0,%1,%2,%3}, {%4,%5,%6,%7}, {%8,%9}, {%0,%1,%2,%3};"
      : "+f"(c[0]), "+f"(c[1]), "+f"(c[2]), "+f"(c[3])
      : "r"(a[0]), "r"(a[1]), "r"(a[2]), "r"(a[3]), "r"(b[0]), "r"(b[1]));
}
__device__ __forceinline__ void ldsm4(unsigned* r, uint32_t a){
    asm volatile("ldmatrix.sync.aligned.m8n8.x4.shared.b16 {%0,%1,%2,%3}, [%4];"
        : "=r"(r[0]), "=r"(r[1]), "=r"(r[2]), "=r"(r[3]) : "r"(a));
}
__device__ __forceinline__ uint32_t smem_u32(const void* p){
    uint32_t a; asm("{ .reg .u64 t; cvta.to.shared.u64 t, %1; cvt.u32.u64 %0, t; }" : "=r"(a) : "l"(p));
    return a;
}
__device__ __forceinline__ void cpa16(uint32_t dst, const __half* src, int srcsize){
    asm volatile("cp.async.cg.shared.global [%0], [%1], 16, %2;"
        :: "r"(dst), "l"(src), "r"(srcsize) : "memory");
}
__device__ __forceinline__ void cp_commit(){ asm volatile("cp.async.commit_group;" ::: "memory"); }
__device__ __forceinline__ void cp_wait2(){ asm volatile("cp.async.wait_group 2;" ::: "memory"); }

// ---------------- prep kernels ----------------
__global__ void whalf(const float* __restrict__ in, __half* __restrict__ outp, int n4){
    int i = blockIdx.x*256 + threadIdx.x;
    if (i >= n4) return;
    float4 v = *(const float4*)(in + (size_t)i*4);
    __half2 h01 = __floats2half2_rn(v.x, v.y);
    __half2 h23 = __floats2half2_rn(v.z, v.w);
    *(uint2*)(outp + (size_t)i*4) = make_uint2(*(unsigned*)&h01, *(unsigned*)&h23);
}

// conv_w [k=8192][n=2048] -> [n][k] fp16
__global__ void convT(const float* __restrict__ cw){
    __shared__ float tl[32][33];
    const int k0 = blockIdx.x*32, n0 = blockIdx.y*32;
    const int tx = threadIdx.x, ty = threadIdx.y;
    #pragma unroll
    for (int d = 0; d < 4; d++)
        tl[ty + d*8][tx] = cw[(size_t)(k0+ty+d*8)*Hsz + n0 + tx];
    __syncthreads();
    #pragma unroll
    for (int d = 0; d < 4; d++)
        d_cwT16[(size_t)(n0+ty+d*8)*(4*Hsz) + k0 + tx] = __float2half_rn(tl[tx][ty+d*8]);
}

// ---------------- small kernels ----------------
__global__ void aexp_kernel(const float* __restrict__ alog) {
    int i = blockIdx.x*256 + threadIdx.x;
    if (i < Hsz*NST) d_Aexp[i] = -expf(alog[i]);
}

__global__ void rmsnorm_kernel(const float* __restrict__ x, const float* __restrict__ w) {
    const int m = blockIdx.x;
    const float* xr = x + (size_t)m*Hsz;
    float ss = 0.f;
    for (int i = threadIdx.x*4; i < Hsz; i += 1024) {
        float4 v = *(const float4*)(xr + i);
        ss += v.x*v.x + v.y*v.y + v.z*v.z + v.w*v.w;
    }
    __shared__ float red[8];
    #pragma unroll
    for (int o = 16; o; o >>= 1) ss += __shfl_xor_sync(0xffffffffu, ss, o);
    if ((threadIdx.x & 31) == 0) red[threadIdx.x >> 5] = ss;
    __syncthreads();
    if (threadIdx.x == 0) {
        float v = 0.f;
        #pragma unroll
        for (int j = 0; j < 8; j++) v += red[j];
        red[0] = rsqrtf(v * (1.0f/Hsz) + 1e-5f);
    }
    __syncthreads();
    const float sc = red[0];
    for (int i = threadIdx.x*4; i < Hsz; i += 1024) {
        float4 v = *(const float4*)(xr + i);
        float4 wv = *(const float4*)(w + i);
        __half2 h01 = __floats2half2_rn(v.x*sc*wv.x, v.y*sc*wv.y);
        __half2 h23 = __floats2half2_rn(v.z*sc*wv.z, v.w*sc*wv.w);
        *(uint2*)(d_h16 + (size_t)m*Hsz + i) = make_uint2(*(unsigned*)&h01, *(unsigned*)&h23);
    }
}

// ====== fp16 tensor GEMM, cp.async 4-stage pipeline, m16n8k16 ======
// Per-warp k-step rotation de-phases LDSM/MMA bursts across warps.
// C = A(M,K) * W(N,K)^T. block 128x256, 512 thr, warp tile 32x64.
// EPI 0: in_proj split (n<H -> fp16 xcp, else -> fp32 z)
// EPI 1: conv bias+silu -> fp32 C
// EPI 2: resid add -> fp32 C
template<int EPI, bool CONVA>
__global__ void __launch_bounds__(512, 1)
gemm_tc(const __half* __restrict__ A, const __half* __restrict__ W,
        float* __restrict__ C, float* __restrict__ C2,
        const float* __restrict__ aux, int K, int lda, int ldc)
{
    extern __shared__ __align__(16) __half sm[];
    const uint32_t smb = smem_u32(sm);
    const int t = threadIdx.x;
    const int lane = t & 31, w = t >> 5;
    const int gid = lane >> 2, tig = lane & 3;
    const int wm = (w & 3) * 32, wn = (w >> 2) * 64;
    const int wrot = w & 3;
    const int n0 = blockIdx.x * TN, m0 = blockIdx.y * TM;
    const int nc = K / KC;

    // cp.async destinations (stage 0), 16B per op = 8 halves
    uint32_t dstA[2], dstB[4];
    int rowA[2], kcA[2], rowB[4], kcB[4];
    #pragma unroll
    for (int i = 0; i < 2; i++) {
        int slot = t + 512*i;
        rowA[i] = slot >> 3; kcA[i] = (slot & 7) * 8;
        dstA[i] = smb + (uint32_t)(rowA[i]*RS + kcA[i])*2;
    }
    #pragma unroll
    for (int i = 0; i < 4; i++) {
        int slot = t + 512*i;
        rowB[i] = slot >> 3; kcB[i] = (slot & 7) * 8;
        dstB[i] = smb + (uint32_t)(OFFB_H + rowB[i]*RS + kcB[i])*2;
    }

    auto issue = [&](int c){
        if (c < nc) {
            const uint32_t so = (uint32_t)(c & (DST-1)) * (STG_H*2);
            const int kb = c * KC;
            if (!CONVA) {
                #pragma unroll
                for (int i = 0; i < 2; i++)
                    cpa16(dstA[i] + so, A + (size_t)(m0 + rowA[i])*lda + kb + kcA[i], 16);
            } else {
                const int tap = kb >> 11, kin = kb & (Hsz-1);
                #pragma unroll
                for (int i = 0; i < 2; i++) {
                    const int m = m0 + rowA[i];
                    int ls = (m & 1023) + tap - 3;
                    const int sz = (ls >= 0) ? 16 : 0;
                    if (ls < 0) ls = 0;
                    cpa16(dstA[i] + so, A + (size_t)((m & ~1023) + ls)*lda + kin + kcA[i], sz);
                }
            }
            #pragma unroll
            for (int i = 0; i < 4; i++)
                cpa16(dstB[i] + so, W + (size_t)(n0 + rowB[i])*K + kb + kcB[i], 16);
        }
        cp_commit();
    };

    // ldmatrix source addresses (stage 0)
    uint32_t a_ad[2], b_ad[4];
    {
        const int arow = (lane & 15), acol = (lane >> 4) * 8;
        #pragma unroll
        for (int mi = 0; mi < 2; mi++)
            a_ad[mi] = smb + (uint32_t)(((wm + mi*16 + arow)*RS + acol))*2;
        const int brow = ((lane & 16) >> 1) + (lane & 7);
        const int bcol = (lane & 8);
        #pragma unroll
        for (int nq = 0; nq < 4; nq++)
            b_ad[nq] = smb + (uint32_t)((OFFB_H + (wn + nq*16 + brow)*RS + bcol))*2;
    }

    float acc[2][8][4];
    #pragma unroll
    for (int mi = 0; mi < 2; mi++)
        #pragma unroll
        for (int ni = 0; ni < 8; ni++)
            #pragma unroll
            for (int q = 0; q < 4; q++) acc[mi][ni][q] = 0.f;

    issue(0); issue(1); issue(2);
    for (int c = 0; c < nc; c++) {
        cp_wait2();
        __syncthreads();
        const uint32_t so = (uint32_t)(c & (DST-1)) * (STG_H*2);
        #pragma unroll
        for (int i = 0; i < 4; i++) {           // 4 x k16, rotated per warp
            const int ks = (i + wrot) & 3;
            unsigned af[2][4], bf[4][4];
            ldsm4(af[0], a_ad[0] + so + ks*32);
            ldsm4(af[1], a_ad[1] + so + ks*32);
            #pragma unroll
            for (int nq = 0; nq < 4; nq++) ldsm4(bf[nq], b_ad[nq] + so + ks*32);
            #pragma unroll
            for (int mi = 0; mi < 2; mi++)
                #pragma unroll
                for (int ni = 0; ni < 8; ni++)
                    mma16(acc[mi][ni], af[mi], &bf[ni>>1][(ni&1)*2]);
        }
        issue(c + DST - 1);
    }

    // epilogue
    #pragma unroll
    for (int mi = 0; mi < 2; mi++) {
        #pragma unroll
        for (int rr = 0; rr < 2; rr++) {
            const int m = m0 + wm + mi*16 + rr*8 + gid;
            #pragma unroll
            for (int ni = 0; ni < 8; ni++) {
                const int n = n0 + wn + ni*8 + tig*2;
                float v0 = acc[mi][ni][rr*2+0];
                float v1 = acc[mi][ni][rr*2+1];
                if (EPI == 0) {
                    if (n < Hsz) {
                        __half2 hp = __floats2half2_rn(v0, v1);
                        *(unsigned*)&d_xcp16[(size_t)m*Hsz + n] = *(unsigned*)&hp;
                    } else {
                        *(float2*)&C2[(size_t)m*ldc + n - Hsz] = make_float2(v0, v1);
                    }
                } else if (EPI == 1) {
                    v0 += aux[n];   v1 += aux[n+1];
                    v0 = v0 / (1.f + __expf(-v0));
                    v1 = v1 / (1.f + __expf(-v1));
                    *(float2*)&C[(size_t)m*ldc + n] = make_float2(v0, v1);
                } else {
                    v0 += aux[(size_t)m*ldc + n];
                    v1 += aux[(size_t)m*ldc + n + 1];
                    *(float2*)&C[(size_t)m*ldc + n] = make_float2(v0, v1);
                }
            }
        }
    }
}

// ---------------- fp32 SIMT GEMM (exact; small ops) ----------------
template<int EPI>
__global__ void __launch_bounds__(256)
gemm_wt(const float* __restrict__ A, const float* __restrict__ W,
        float* __restrict__ C, int M, int N, int K,
        int lda, int ldb, int ldc,
        const float* __restrict__ bias)
{
    __shared__ float As[8][128];
    __shared__ float Bs[8][128];
    const int t  = threadIdx.x;
    const int n0 = blockIdx.x * 128;
    const int m0 = blockIdx.y * 128;
    const int kslice = K / gridDim.z;
    const int kbeg = blockIdx.z * kslice;
    const int KT = kslice >> 3;

    const int ar = t >> 1;
    const int ak = (t & 1) * 4;
    const float* Ap = A + (size_t)(m0 + ar)*lda + kbeg + ak;
    const bool wok = (n0 + ar) < N;
    const float* Wp = W + (size_t)(n0 + ar)*ldb + kbeg + ak;

    float* Cb = C;
    if (EPI == 4) Cb = C + (size_t)blockIdx.z * M * ldc;

    const int tx = t & 15, ty = t >> 4;
    float acc[8][8];
    #pragma unroll
    for (int i = 0; i < 8; i++)
        #pragma unroll
        for (int j = 0; j < 8; j++) acc[i][j] = 0.f;

    float4 pa = *(const float4*)Ap;
    float4 pb = wok ? *(const float4*)Wp : make_float4(0.f,0.f,0.f,0.f);

    for (int kt = 0; kt < KT; ++kt) {
        As[ak+0][ar]=pa.x; As[ak+1][ar]=pa.y; As[ak+2][ar]=pa.z; As[ak+3][ar]=pa.w;
        Bs[ak+0][ar]=pb.x; Bs[ak+1][ar]=pb.y; Bs[ak+2][ar]=pb.z; Bs[ak+3][ar]=pb.w;
        __syncthreads();
        if (kt + 1 < KT) {
            pa = *(const float4*)(Ap + (size_t)(kt+1)*8);
            pb = wok ? *(const float4*)(Wp + (size_t)(kt+1)*8) : make_float4(0.f,0.f,0.f,0.f);
        }
        #pragma unroll
        for (int kk = 0; kk < 8; kk++) {
            float a[8], b[8];
            *(float4*)&a[0] = *(const float4*)&As[kk][ty*8];
            *(float4*)&a[4] = *(const float4*)&As[kk][ty*8+4];
            *(float4*)&b[0] = *(const float4*)&Bs[kk][tx*8];
            *(float4*)&b[4] = *(const float4*)&Bs[kk][tx*8+4];
            #pragma unroll
            for (int i = 0; i < 8; i++)
                #pragma unroll
                for (int j = 0; j < 8; j++)
                    acc[i][j] = fmaf(a[i], b[j], acc[i][j]);
        }
        __syncthreads();
    }

    #pragma unroll
    for (int i = 0; i < 8; i++) {
        const int m = m0 + ty*8 + i;
        #pragma unroll
        for (int j = 0; j < 8; j++) {
            const int n = n0 + tx*8 + j;
            if (n < N) {
                float v = acc[i][j];
                if (EPI == 2) { v += bias[n]; v = (v > 20.f) ? v : log1pf(__expf(v)); }
                Cb[(size_t)m*ldc + n] = v;
            }
        }
    }
}

__global__ void reduce_dbc() {
    int i = blockIdx.x*256 + threadIdx.x;
    if (i < Msz*96) {
        float s = 0.f;
        #pragma unroll
        for (int z = 0; z < DBC_SPLITS; z++) s += d_dbcp[(size_t)z*Msz*96 + i];
        d_dbc[i] = s;
    }
}

// ---------------- chunked selective scan ----------------
__global__ void __launch_bounds__(128) scan_pass1() {
    __shared__ float sB[CHUNK][NST];
    const int bid = blockIdx.x;
    const int ht = bid & 15;
    const int c  = (bid >> 4) & 7;
    const int b  = bid >> 7;
    const int h  = ht*128 + threadIdx.x;
    const int mbase = b*Lsz + c*CHUNK;

    for (int j = threadIdx.x; j < CHUNK*NST; j += 128) {
        int l = j >> 4, n = j & 15;
        sB[l][n] = d_dbc[(size_t)(mbase+l)*96 + 64 + n];
    }
    __syncthreads();

    float a[NST], p[NST], s[NST];
    #pragma unroll
    for (int n = 0; n < NST; n++) { a[n] = d_Aexp[h*NST + n]; p[n] = 1.f; s[n] = 0.f; }

    float dl = d_delta[(size_t)mbase*Hsz + h];
    float xv = d_xc[(size_t)mbase*Hsz + h];
    for (int l = 0; l < CHUNK; l++) {
        float dln = 0.f, xvn = 0.f;
        if (l + 1 < CHUNK) {
            dln = d_delta[(size_t)(mbase+l+1)*Hsz + h];
            xvn = d_xc[(size_t)(mbase+l+1)*Hsz + h];
        }
        const float du = dl * xv;
        #pragma unroll
        for (int n = 0; n < NST; n++) {
            float r = __expf(dl * a[n]);
            p[n] *= r;
            s[n] = fmaf(r, s[n], du * sB[l][n]);
        }
        dl = dln; xv = xvn;
    }
    size_t base = ((size_t)(b*NCHUNK + c)*Hsz + h)*NST;
    #pragma unroll
    for (int n = 0; n < NST; n++) { d_P[base+n] = p[n]; d_S[base+n] = s[n]; }
}

__global__ void scan_pass2() {
    int idx = blockIdx.x*256 + threadIdx.x;
    if (idx >= Bsz*Hsz*NST) return;
    int b  = idx / (Hsz*NST);
    int hn = idx % (Hsz*NST);
    float st = 0.f;
    for (int c = 0; c < NCHUNK; c++) {
        size_t o = (size_t)(b*NCHUNK + c)*Hsz*NST + hn;
        d_I[o] = st;
        st = d_P[o]*st + d_S[o];
    }
}

__global__ void __launch_bounds__(128) scan_pass3(const float* __restrict__ Din) {
    __shared__ float sBC[CHUNK][2*NST];
    const int bid = blockIdx.x;
    const int ht = bid & 15;
    const int c  = (bid >> 4) & 7;
    const int b  = bid >> 7;
    const int h  = ht*128 + threadIdx.x;
    const int mbase = b*Lsz + c*CHUNK;

    for (int j = threadIdx.x; j < CHUNK*2*NST; j += 128) {
        int l = j >> 5, cc = j & 31;
        sBC[l][cc] = d_dbc[(size_t)(mbase+l)*96 + 64 + cc];
    }
    __syncthreads();

    float a[NST], s[NST];
    size_t base = ((size_t)(b*NCHUNK + c)*Hsz + h)*NST;
    #pragma unroll
    for (int n = 0; n < NST; n++) { a[n] = d_Aexp[h*NST + n]; s[n] = d_I[base+n]; }
    const float Dh = Din[h];

    float dl = d_delta[(size_t)mbase*Hsz + h];
    float xv = d_xc[(size_t)mbase*Hsz + h];
    for (int l = 0; l < CHUNK; l++) {
        float dln = 0.f, xvn = 0.f;
        if (l + 1 < CHUNK) {
            dln = d_delta[(size_t)(mbase+l+1)*Hsz + h];
            xvn = d_xc[(size_t)(mbase+l+1)*Hsz + h];
        }
        const float du = dl * xv;
        float y = 0.f;
        #pragma unroll
        for (int n = 0; n < NST; n++) {
            float r = __expf(dl * a[n]);
            s[n] = fmaf(r, s[n], du * sBC[l][n]);
            y = fmaf(s[n], sBC[l][NST+n], y);
        }
        y = fmaf(Dh, xv, y);
        const int m = mbase + l;
        float z = d_z[(size_t)m*Hsz + h];
        float sz = z / (1.f + __expf(-z));
        d_g16[(size_t)m*Hsz + h] = __float2half_rn(y * sz);
        dl = dln; xv = xvn;
    }
}

// ---------------- launch ----------------
extern "C" void kernel_launch(void* const* d_in, const int* in_sizes, int n_in,
                              void* d_out, int out_size) {
    const float* x          = (const float*)d_in[0];
    const float* norm_w     = (const float*)d_in[1];
    const float* in_proj_w  = (const float*)d_in[2];
    const float* conv_w     = (const float*)d_in[3];
    const float* conv_b     = (const float*)d_in[4];
    const float* x_proj_w   = (const float*)d_in[5];
    const float* dt_proj_w  = (const float*)d_in[6];
    const float* dt_proj_b  = (const float*)d_in[7];
    const float* A_log      = (const float*)d_in[8];
    const float* Dv         = (const float*)d_in[9];
    const float* out_proj_w = (const float*)d_in[10];
    float* out = (float*)d_out;

    static int attr_done = 0;
    if (!attr_done) {
        cudaFuncSetAttribute(gemm_tc<0,false>, cudaFuncAttributeMaxDynamicSharedMemorySize, SMEM_TOT);
        cudaFuncSetAttribute(gemm_tc<1,true >, cudaFuncAttributeMaxDynamicSharedMemorySize, SMEM_TOT);
        cudaFuncSetAttribute(gemm_tc<2,false>, cudaFuncAttributeMaxDynamicSharedMemorySize, SMEM_TOT);
        attr_done = 1;
    }

    __half *p_h16, *p_xcp16, *p_g16, *p_ipw16, *p_opw16, *p_cwT16;
    float *p_z, *p_xc, *p_dbc, *p_dbcp, *p_delta;
    cudaGetSymbolAddress((void**)&p_h16, d_h16);
    cudaGetSymbolAddress((void**)&p_xcp16, d_xcp16);
    cudaGetSymbolAddress((void**)&p_g16, d_g16);
    cudaGetSymbolAddress((void**)&p_ipw16, d_ipw16);
    cudaGetSymbolAddress((void**)&p_opw16, d_opw16);
    cudaGetSymbolAddress((void**)&p_cwT16, d_cwT16);
    cudaGetSymbolAddress((void**)&p_z, d_z);
    cudaGetSymbolAddress((void**)&p_xc, d_xc);
    cudaGetSymbolAddress((void**)&p_dbc, d_dbc);
    cudaGetSymbolAddress((void**)&p_dbcp, d_dbcp);
    cudaGetSymbolAddress((void**)&p_delta, d_delta);

    // 0. prep: fp16 weights (+ conv transpose)
    whalf<<<(2*Hsz*Hsz/4 + 255)/256, 256>>>(in_proj_w, p_ipw16, 2*Hsz*Hsz/4);
    whalf<<<(Hsz*Hsz/4 + 255)/256, 256>>>(out_proj_w, p_opw16, Hsz*Hsz/4);
    convT<<<dim3(4*Hsz/32, Hsz/32), dim3(32,8)>>>(conv_w);
    aexp_kernel<<<(Hsz*NST + 255)/256, 256>>>(A_log);
    // 1. rmsnorm (emits fp16 h)
    rmsnorm_kernel<<<Msz, 256>>>(x, norm_w);
    // 2. in_proj: xz = h @ W^T (M=2048, N=4096, K=2048) -> xcp16 | z(fp32)
    gemm_tc<0,false><<<dim3(2*Hsz/TN, Msz/TM), 512, SMEM_TOT>>>(
        p_h16, p_ipw16, nullptr, p_z, nullptr, Hsz, Hsz, Hsz);
    // 3. conv: xc = silu(conv(xcp) + b)  (K=8192 virtual over 4 taps)
    gemm_tc<1,true><<<dim3(Hsz/TN, Msz/TM), 512, SMEM_TOT>>>(
        p_xcp16, p_cwT16, p_xc, nullptr, conv_b, 4*Hsz, Hsz, Hsz);
    // 4. dBC = xc @ x_proj_w.T  (exact fp32, split-K)
    gemm_wt<4><<<dim3(1,16,DBC_SPLITS), 256>>>(p_xc, x_proj_w, p_dbcp,
                                               Msz, 96, Hsz, Hsz, Hsz, 96, nullptr);
    reduce_dbc<<<(Msz*96 + 255)/256, 256>>>();
    // 5. delta = softplus(dBC[:, :64] @ dt_proj_w.T + b)  (exact fp32)
    gemm_wt<2><<<dim3(16,16,1), 256>>>(p_dbc, dt_proj_w, p_delta,
                                       Msz, Hsz, 64, 96, 64, Hsz, dt_proj_b);
    // 6. chunked selective scan -> g (fp16)
    scan_pass1<<<Bsz*NCHUNK*(Hsz/128), 128>>>();
    scan_pass2<<<(Bsz*Hsz*NST + 255)/256, 256>>>();
    scan_pass3<<<Bsz*NCHUNK*(Hsz/128), 128>>>(Dv);
    // 7. out = x + g @ out_proj_w.T
    gemm_tc<2,false><<<dim3(Hsz/TN, Msz/TM), 512, SMEM_TOT>>>(
        p_g16, p_opw16, out, nullptr, x, Hsz, Hsz, Hsz);
}